// round 1
// baseline (speedup 1.0000x reference)
#include <cuda_runtime.h>

#define BB 64
#define TT 256
#define CC 384
#define HH 6
#define DD 64
#define BT (BB*TT)         // 16384
#define NQKV (3*HH*DD)     // 1152

// ---- scratch (no runtime allocation allowed) ----
__device__ float g_Wbig[CC*NQKV];       // packed [C, 3*H*D]
__device__ float g_q[BB*HH*TT*DD];      // [B,H,T,D]
__device__ float g_k[BB*HH*TT*DD];
__device__ float g_v[BB*HH*TT*DD];
__device__ float g_att[BT*CC];          // [B,T,H*D] concat-heads

// ---------------------------------------------------------------------------
// Pack Wq/Wk/Wv [H,C,D] into one row-major [C, 3*H*D] matrix so QKV is 1 GEMM.
// ---------------------------------------------------------------------------
__global__ void pack_w_kernel(const float* __restrict__ Wq,
                              const float* __restrict__ Wk,
                              const float* __restrict__ Wv) {
    int idx = blockIdx.x * blockDim.x + threadIdx.x;
    if (idx >= CC*NQKV) return;
    int c = idx / NQKV, j = idx % NQKV;
    int proj = j / (HH*DD), r = j % (HH*DD);
    int h = r / DD, d = r % DD;
    const float* W = (proj == 0) ? Wq : (proj == 1) ? Wk : Wv;
    g_Wbig[idx] = W[(h*CC + c)*DD + d];
}

// ---------------------------------------------------------------------------
// SGEMM: QKV = X[16384,384] @ Wbig[384,1152], scattered to g_q/g_k/g_v [B,H,T,D]
// 128x128 block tile, BK=16, 256 threads, 8x8 per-thread microtile.
// ---------------------------------------------------------------------------
__global__ __launch_bounds__(256) void gemm_qkv_kernel(const float* __restrict__ X) {
    __shared__ float As[16][128];
    __shared__ float Bs[16][128];
    int tid = threadIdx.x;
    int tx = tid & 15, ty = tid >> 4;
    const int row0 = blockIdx.y * 128;
    const int col0 = blockIdx.x * 128;

    float acc[8][8];
    #pragma unroll
    for (int i = 0; i < 8; i++)
        #pragma unroll
        for (int j = 0; j < 8; j++) acc[i][j] = 0.f;

    for (int k0 = 0; k0 < CC; k0 += 16) {
        // A tile: 128 rows x 16 k (coalesced float4 along k, transposed store)
        {
            int m  = tid >> 2;          // 0..63
            int kv = (tid & 3) * 4;     // 0,4,8,12
            #pragma unroll
            for (int rep = 0; rep < 2; rep++) {
                int mm = m + rep * 64;
                float4 a = *(const float4*)&X[(size_t)(row0 + mm)*CC + k0 + kv];
                As[kv+0][mm] = a.x; As[kv+1][mm] = a.y;
                As[kv+2][mm] = a.z; As[kv+3][mm] = a.w;
            }
        }
        // B tile: 16 k x 128 n (coalesced float4 along n)
        {
            int kk = tid >> 5;          // 0..7
            int n4 = (tid & 31) * 4;
            #pragma unroll
            for (int rep = 0; rep < 2; rep++) {
                int kkk = kk + rep * 8;
                *(float4*)&Bs[kkk][n4] =
                    *(const float4*)&g_Wbig[(size_t)(k0 + kkk)*NQKV + col0 + n4];
            }
        }
        __syncthreads();
        #pragma unroll
        for (int kk = 0; kk < 16; kk++) {
            float a[8], b[8];
            *(float4*)&a[0] = *(float4*)&As[kk][ty*4];
            *(float4*)&a[4] = *(float4*)&As[kk][64 + ty*4];
            *(float4*)&b[0] = *(float4*)&Bs[kk][tx*4];
            *(float4*)&b[4] = *(float4*)&Bs[kk][64 + tx*4];
            #pragma unroll
            for (int i = 0; i < 8; i++)
                #pragma unroll
                for (int j = 0; j < 8; j++)
                    acc[i][j] = fmaf(a[i], b[j], acc[i][j]);
        }
        __syncthreads();
    }

    // Scatter-store to q/k/v in [B,H,T,D]
    #pragma unroll
    for (int i = 0; i < 8; i++) {
        int mm = row0 + ((i < 4) ? (ty*4 + i) : (64 + ty*4 + (i - 4)));
        int b = mm / TT, t = mm % TT;
        #pragma unroll
        for (int j = 0; j < 8; j++) {
            int nn = col0 + ((j < 4) ? (tx*4 + j) : (64 + tx*4 + (j - 4)));
            int proj = nn / (HH*DD);
            int r2 = nn % (HH*DD);
            int h = r2 / DD, d = r2 % DD;
            float* dst = (proj == 0) ? g_q : (proj == 1) ? g_k : g_v;
            dst[(size_t)((b*HH + h)*TT + t)*DD + d] = acc[i][j];
        }
    }
}

// ---------------------------------------------------------------------------
// Fused causal attention: one block per (b,h), one thread per query row.
// K,V staged in 128KB smem; online softmax; causal mask = per-thread loop bound.
// ---------------------------------------------------------------------------
__global__ __launch_bounds__(256) void attn_kernel() {
    extern __shared__ float smem[];
    float* Ks = smem;             // [T*D]
    float* Vs = smem + TT*DD;     // [T*D]
    int bh  = blockIdx.x;         // b*H + h
    int tid = threadIdx.x;

    const float* kbase = g_k + (size_t)bh*TT*DD;
    const float* vbase = g_v + (size_t)bh*TT*DD;
    for (int i = tid*4; i < TT*DD; i += 256*4) {
        *(float4*)&Ks[i] = *(const float4*)&kbase[i];
        *(float4*)&Vs[i] = *(const float4*)&vbase[i];
    }
    __syncthreads();

    int t = tid;
    float4 q4[16];
    const float4* qrow = (const float4*)(g_q + (size_t)(bh*TT + t)*DD);
    #pragma unroll
    for (int i = 0; i < 16; i++) q4[i] = qrow[i];

    float4 o4[16];
    #pragma unroll
    for (int i = 0; i < 16; i++) o4[i] = make_float4(0.f, 0.f, 0.f, 0.f);

    float m = -1e30f, l = 0.f;
    const float scale = 0.125f;   // 1/sqrt(64)

    for (int s = 0; s <= t; s++) {
        const float4* krow = (const float4*)&Ks[s*DD];
        float sc = 0.f;
        #pragma unroll
        for (int i = 0; i < 16; i++) {
            float4 kk = krow[i];
            sc = fmaf(q4[i].x, kk.x, sc);
            sc = fmaf(q4[i].y, kk.y, sc);
            sc = fmaf(q4[i].z, kk.z, sc);
            sc = fmaf(q4[i].w, kk.w, sc);
        }
        sc *= scale;
        float mnew  = fmaxf(m, sc);
        float alpha = __expf(m - mnew);
        float p     = __expf(sc - mnew);
        l = l * alpha + p;
        const float4* vrow = (const float4*)&Vs[s*DD];
        #pragma unroll
        for (int i = 0; i < 16; i++) {
            float4 vv = vrow[i];
            o4[i].x = fmaf(o4[i].x, alpha, 0.f) + p*vv.x;
            o4[i].y = o4[i].y*alpha + p*vv.y;
            o4[i].z = o4[i].z*alpha + p*vv.z;
            o4[i].w = o4[i].w*alpha + p*vv.w;
        }
        m = mnew;
    }

    float inv = 1.f / l;
    int b = bh / HH, h = bh % HH;
    float* dst = g_att + (size_t)(b*TT + t)*CC + h*DD;
    #pragma unroll
    for (int i = 0; i < 16; i++) {
        float4 o = o4[i];
        o.x *= inv; o.y *= inv; o.z *= inv; o.w *= inv;
        *(float4*)&dst[i*4] = o;
    }
}

// ---------------------------------------------------------------------------
// Output projection: out[16384,384] = g_att @ Wp^T + bp
// ---------------------------------------------------------------------------
__global__ __launch_bounds__(256) void gemm_proj_kernel(const float* __restrict__ Wp,
                                                        const float* __restrict__ bp,
                                                        float* __restrict__ out) {
    __shared__ float As[16][128];
    __shared__ float Bs[16][128];
    int tid = threadIdx.x;
    int tx = tid & 15, ty = tid >> 4;
    const int row0 = blockIdx.y * 128;
    const int col0 = blockIdx.x * 128;

    float acc[8][8];
    #pragma unroll
    for (int i = 0; i < 8; i++)
        #pragma unroll
        for (int j = 0; j < 8; j++) acc[i][j] = 0.f;

    for (int k0 = 0; k0 < CC; k0 += 16) {
        {
            int m  = tid >> 2;
            int kv = (tid & 3) * 4;
            #pragma unroll
            for (int rep = 0; rep < 2; rep++) {
                int mm = m + rep * 64;
                float4 a = *(const float4*)&g_att[(size_t)(row0 + mm)*CC + k0 + kv];
                As[kv+0][mm] = a.x; As[kv+1][mm] = a.y;
                As[kv+2][mm] = a.z; As[kv+3][mm] = a.w;
            }
        }
        {
            // B[k][n] = Wp[n][k] (y = x @ Wp^T); read float4 along k, transpose-store
            int n  = tid >> 2;
            int kv = (tid & 3) * 4;
            #pragma unroll
            for (int rep = 0; rep < 2; rep++) {
                int nn = n + rep * 64;
                float4 w = *(const float4*)&Wp[(size_t)(col0 + nn)*CC + k0 + kv];
                Bs[kv+0][nn] = w.x; Bs[kv+1][nn] = w.y;
                Bs[kv+2][nn] = w.z; Bs[kv+3][nn] = w.w;
            }
        }
        __syncthreads();
        #pragma unroll
        for (int kk = 0; kk < 16; kk++) {
            float a[8], b[8];
            *(float4*)&a[0] = *(float4*)&As[kk][ty*4];
            *(float4*)&a[4] = *(float4*)&As[kk][64 + ty*4];
            *(float4*)&b[0] = *(float4*)&Bs[kk][tx*4];
            *(float4*)&b[4] = *(float4*)&Bs[kk][64 + tx*4];
            #pragma unroll
            for (int i = 0; i < 8; i++)
                #pragma unroll
                for (int j = 0; j < 8; j++)
                    acc[i][j] = fmaf(a[i], b[j], acc[i][j]);
        }
        __syncthreads();
    }

    #pragma unroll
    for (int i = 0; i < 8; i++) {
        int mm = row0 + ((i < 4) ? (ty*4 + i) : (64 + ty*4 + (i - 4)));
        #pragma unroll
        for (int j = 0; j < 8; j++) {
            int nn = col0 + ((j < 4) ? (tx*4 + j) : (64 + tx*4 + (j - 4)));
            out[(size_t)mm*CC + nn] = acc[i][j] + __ldg(&bp[nn]);
        }
    }
}

// ---------------------------------------------------------------------------
extern "C" void kernel_launch(void* const* d_in, const int* in_sizes, int n_in,
                              void* d_out, int out_size) {
    const float* x  = (const float*)d_in[0];
    const float* Wq = (const float*)d_in[1];
    const float* Wk = (const float*)d_in[2];
    const float* Wv = (const float*)d_in[3];
    const float* Wp = (const float*)d_in[4];
    const float* bp = (const float*)d_in[5];
    float* out = (float*)d_out;

    // 1) pack weights into one [C, 3HD] GEMM operand
    pack_w_kernel<<<(CC*NQKV + 255)/256, 256>>>(Wq, Wk, Wv);

    // 2) QKV projection GEMM
    dim3 g1(NQKV/128, BT/128);   // (9, 128)
    gemm_qkv_kernel<<<g1, 256>>>(x);

    // 3) fused causal attention (needs >48KB dynamic smem)
    int smem_bytes = 2 * TT * DD * (int)sizeof(float);   // 128 KB
    cudaFuncSetAttribute(attn_kernel, cudaFuncAttributeMaxDynamicSharedMemorySize, smem_bytes);
    attn_kernel<<<BB*HH, 256, smem_bytes>>>();

    // 4) output projection + bias
    dim3 g2(CC/128, BT/128);     // (3, 128)
    gemm_proj_kernel<<<g2, 256>>>(Wp, bp, out);
}

// round 6
// speedup vs baseline: 1.7858x; 1.7858x over previous
#include <cuda_runtime.h>
#include <cuda_bf16.h>
#include <cstdint>

#define BB 64
#define TT 256
#define CC 384
#define HH 6
#define DD 64
#define BT (BB*TT)         // 16384
#define NQKV (3*HH*DD)     // 1152
#define PITCH 40           // bf16 elems per smem row (80B, conflict-free)
#define TILE_B (128*PITCH*2)  // 10240 bytes per 128x32 tile

// ---------------- static scratch ----------------
__device__ __align__(128) __nv_bfloat16 g_Xhi[(size_t)BT*CC],   g_Xlo[(size_t)BT*CC];
__device__ __align__(128) __nv_bfloat16 g_Wthi[(size_t)NQKV*CC], g_Wtlo[(size_t)NQKV*CC];
__device__ __align__(128) __nv_bfloat16 g_Athi[(size_t)BT*CC],  g_Atlo[(size_t)BT*CC];
__device__ __align__(128) __nv_bfloat16 g_Wphi[(size_t)CC*CC],  g_Wplo[(size_t)CC*CC];
__device__ __align__(128) float g_q[(size_t)BB*HH*TT*DD];
__device__ __align__(128) float g_kk[(size_t)BB*HH*TT*DD];
__device__ __align__(128) float g_vv[(size_t)BB*HH*TT*DD];

// ---------------- helpers ----------------
__device__ __forceinline__ void ldgsts16(uint32_t s, const void* g) {
    asm volatile("cp.async.cg.shared.global [%0], [%1], 16;" :: "r"(s), "l"(g));
}
__device__ __forceinline__ void mma_bf16(float* c, const uint32_t* a, const uint32_t* b) {
    asm volatile("mma.sync.aligned.m16n8k16.row.col.f32.bf16.bf16.f32 "
                 "{%0,%1,%2,%3}, {%4,%5,%6,%7}, {%8,%9}, {%0,%1,%2,%3};"
                 : "+f"(c[0]), "+f"(c[1]), "+f"(c[2]), "+f"(c[3])
                 : "r"(a[0]), "r"(a[1]), "r"(a[2]), "r"(a[3]),
                   "r"(b[0]), "r"(b[1]));
}

// ---------------- split / pack kernels ----------------
__global__ void split_x(const float* __restrict__ src) {
    int i = (blockIdx.x * blockDim.x + threadIdx.x) * 8;
    if (i >= BT*CC) return;
    float4 v0 = *(const float4*)(src + i);
    float4 v1 = *(const float4*)(src + i + 4);
    __nv_bfloat16 h[8], l[8];
    float vv[8] = {v0.x,v0.y,v0.z,v0.w,v1.x,v1.y,v1.z,v1.w};
    #pragma unroll
    for (int j = 0; j < 8; j++) {
        h[j] = __float2bfloat16(vv[j]);
        l[j] = __float2bfloat16(vv[j] - __bfloat162float(h[j]));
    }
    *(uint4*)(g_Xhi + i) = *(uint4*)h;
    *(uint4*)(g_Xlo + i) = *(uint4*)l;
}
__global__ void split_wp(const float* __restrict__ Wp) {
    int i = (blockIdx.x * blockDim.x + threadIdx.x) * 8;
    if (i >= CC*CC) return;
    float4 v0 = *(const float4*)(Wp + i);
    float4 v1 = *(const float4*)(Wp + i + 4);
    __nv_bfloat16 h[8], l[8];
    float vv[8] = {v0.x,v0.y,v0.z,v0.w,v1.x,v1.y,v1.z,v1.w};
    #pragma unroll
    for (int j = 0; j < 8; j++) {
        h[j] = __float2bfloat16(vv[j]);
        l[j] = __float2bfloat16(vv[j] - __bfloat162float(h[j]));
    }
    *(uint4*)(g_Wphi + i) = *(uint4*)h;
    *(uint4*)(g_Wplo + i) = *(uint4*)l;
}
// Pack Wq/Wk/Wv [H,C,D] -> transposed [N=3HD][K=C], split hi/lo
__global__ void pack_wt_kernel(const float* __restrict__ Wq,
                               const float* __restrict__ Wk,
                               const float* __restrict__ Wv) {
    int idx = blockIdx.x * blockDim.x + threadIdx.x;
    if (idx >= NQKV * CC) return;
    int n = idx / CC, c = idx % CC;
    int proj = n / (HH * DD), r = n % (HH * DD);
    int h = r / DD, d = r % DD;
    const float* W = (proj == 0) ? Wq : (proj == 1) ? Wk : Wv;
    float v = W[((size_t)h * CC + c) * DD + d];
    __nv_bfloat16 hi = __float2bfloat16(v);
    g_Wthi[idx] = hi;
    g_Wtlo[idx] = __float2bfloat16(v - __bfloat162float(hi));
}

// ---------------------------------------------------------------------------
// HMMA GEMM: D[m][n] = sum_k A[m,k]*Bt[n,k], bf16 hi/lo 3-product, fp32 acc.
// 128x128 CTA tile, BK=32, double-buffered cp.async, 8 warps (4m x 2n).
// MODE 0: A=Xsplit, B=Wtsplit, scatter to q/k/v.  MODE 1: A=Attsplit, B=Wpsplit, +bias -> out.
// ---------------------------------------------------------------------------
template<int MODE>
__global__ __launch_bounds__(256, 2) void gemm_tc(const float* __restrict__ bp,
                                                  float* __restrict__ outp) {
    extern __shared__ __align__(128) char sm[];
    const __nv_bfloat16* Ahi = (MODE == 0) ? g_Xhi  : g_Athi;
    const __nv_bfloat16* Alo = (MODE == 0) ? g_Xlo  : g_Atlo;
    const __nv_bfloat16* Bhi = (MODE == 0) ? g_Wthi : g_Wphi;
    const __nv_bfloat16* Blo = (MODE == 0) ? g_Wtlo : g_Wplo;

    const int tid = threadIdx.x, lane = tid & 31, wid = tid >> 5;
    const int wm = wid & 3, wn = wid >> 2;
    const int lr = lane >> 2, lc = lane & 3;
    const int row0 = blockIdx.y * 128, col0 = blockIdx.x * 128;

    const int r0 = tid >> 2, sg = tid & 3;
    const uint32_t sbase = (uint32_t)__cvta_generic_to_shared(sm);

    auto load_stage = [&](int buf, int k0) {
        uint32_t st = sbase + buf * 4 * TILE_B;
        #pragma unroll
        for (int rep = 0; rep < 2; rep++) {
            int row = r0 + rep * 64;
            uint32_t so = row * (PITCH * 2) + sg * 16;
            size_t goA = (size_t)(row0 + row) * CC + k0 + sg * 8;
            size_t goB = (size_t)(col0 + row) * CC + k0 + sg * 8;
            ldgsts16(st + 0*TILE_B + so, Ahi + goA);
            ldgsts16(st + 1*TILE_B + so, Alo + goA);
            ldgsts16(st + 2*TILE_B + so, Bhi + goB);
            ldgsts16(st + 3*TILE_B + so, Blo + goB);
        }
    };

    float acc[2][8][4];
    #pragma unroll
    for (int i = 0; i < 2; i++)
        #pragma unroll
        for (int j = 0; j < 8; j++)
            #pragma unroll
            for (int r = 0; r < 4; r++) acc[i][j][r] = 0.f;

    load_stage(0, 0);
    asm volatile("cp.async.commit_group;" ::: "memory");

    for (int kc = 0; kc < 12; kc++) {
        int buf = kc & 1;
        if (kc < 11) {
            load_stage(buf ^ 1, (kc + 1) * 32);
            asm volatile("cp.async.commit_group;" ::: "memory");
            asm volatile("cp.async.wait_group 1;" ::: "memory");
        } else {
            asm volatile("cp.async.wait_group 0;" ::: "memory");
        }
        __syncthreads();

        const char* base = sm + buf * 4 * TILE_B;
        #pragma unroll
        for (int ks = 0; ks < 2; ks++) {
            const int kb = ks * 16;
            uint32_t ah[2][4], al[2][4];
            #pragma unroll
            for (int i = 0; i < 2; i++) {
                const char* p = base + ((wm*32 + i*16 + lr) * PITCH + kb + lc*2) * 2;
                ah[i][0] = *(const uint32_t*)(p);
                ah[i][1] = *(const uint32_t*)(p + 8 * PITCH * 2);
                ah[i][2] = *(const uint32_t*)(p + 16);
                ah[i][3] = *(const uint32_t*)(p + 8 * PITCH * 2 + 16);
                const char* q = p + TILE_B;
                al[i][0] = *(const uint32_t*)(q);
                al[i][1] = *(const uint32_t*)(q + 8 * PITCH * 2);
                al[i][2] = *(const uint32_t*)(q + 16);
                al[i][3] = *(const uint32_t*)(q + 8 * PITCH * 2 + 16);
            }
            #pragma unroll
            for (int j = 0; j < 8; j++) {
                const char* p = base + 2*TILE_B +
                                ((wn*64 + j*8 + lr) * PITCH + kb + lc*2) * 2;
                uint32_t bh[2], bl[2];
                bh[0] = *(const uint32_t*)(p);
                bh[1] = *(const uint32_t*)(p + 16);
                bl[0] = *(const uint32_t*)(p + TILE_B);
                bl[1] = *(const uint32_t*)(p + TILE_B + 16);
                #pragma unroll
                for (int i = 0; i < 2; i++) {
                    mma_bf16(acc[i][j], ah[i], bh);
                    mma_bf16(acc[i][j], ah[i], bl);
                    mma_bf16(acc[i][j], al[i], bh);
                }
            }
        }
        __syncthreads();
    }

    // epilogue
    #pragma unroll
    for (int i = 0; i < 2; i++) {
        int m0 = row0 + wm*32 + i*16 + lr;
        #pragma unroll
        for (int j = 0; j < 8; j++) {
            int nn = col0 + wn*64 + j*8 + lc*2;
            if (MODE == 0) {
                int proj = nn / (HH*DD);
                int rem  = nn % (HH*DD);
                int h = rem / DD, d = rem % DD;
                float* basep = (proj == 0) ? g_q : (proj == 1) ? g_kk : g_vv;
                int b = m0 / TT, t = m0 % TT;
                *(float2*)(basep + ((size_t)((b*HH + h)*TT + t)) * DD + d) =
                    make_float2(acc[i][j][0], acc[i][j][1]);
                *(float2*)(basep + ((size_t)((b*HH + h)*TT + t + 8)) * DD + d) =
                    make_float2(acc[i][j][2], acc[i][j][3]);
            } else {
                float2 bb = *(const float2*)(bp + nn);
                *(float2*)(outp + (size_t)m0 * CC + nn) =
                    make_float2(acc[i][j][0] + bb.x, acc[i][j][1] + bb.y);
                *(float2*)(outp + (size_t)(m0 + 8) * CC + nn) =
                    make_float2(acc[i][j][2] + bb.x, acc[i][j][3] + bb.y);
            }
        }
    }
}

// ---------------------------------------------------------------------------
// Fused causal attention (fp32 SIMT): block per (b,h), thread per query row.
// Epilogue writes bf16 hi/lo split directly (FULL D=64: 8 iterations x 8 elems).
// ---------------------------------------------------------------------------
__global__ __launch_bounds__(256) void attn_kernel() {
    extern __shared__ float smf[];
    float* Ks = smf;
    float* Vs = smf + TT * DD;
    int bh = blockIdx.x;
    int tid = threadIdx.x;

    const float* kbase = g_kk + (size_t)bh * TT * DD;
    const float* vbase = g_vv + (size_t)bh * TT * DD;
    for (int i = tid * 4; i < TT * DD; i += 256 * 4) {
        *(float4*)&Ks[i] = *(const float4*)&kbase[i];
        *(float4*)&Vs[i] = *(const float4*)&vbase[i];
    }
    __syncthreads();

    int t = tid;
    float4 q4[16];
    const float4* qrow = (const float4*)(g_q + (size_t)(bh * TT + t) * DD);
    #pragma unroll
    for (int i = 0; i < 16; i++) q4[i] = qrow[i];

    float4 o4[16];
    #pragma unroll
    for (int i = 0; i < 16; i++) o4[i] = make_float4(0.f, 0.f, 0.f, 0.f);

    float m = -1e30f, l = 0.f;
    const float scale = 0.125f;

    for (int s = 0; s <= t; s++) {
        const float4* krow = (const float4*)&Ks[s * DD];
        float a0 = 0.f, a1 = 0.f, a2 = 0.f, a3 = 0.f;
        #pragma unroll
        for (int i = 0; i < 16; i += 4) {
            float4 k0 = krow[i], k1 = krow[i+1], k2 = krow[i+2], k3 = krow[i+3];
            a0 = fmaf(q4[i].x,   k0.x, a0); a0 = fmaf(q4[i].y,   k0.y, a0);
            a0 = fmaf(q4[i].z,   k0.z, a0); a0 = fmaf(q4[i].w,   k0.w, a0);
            a1 = fmaf(q4[i+1].x, k1.x, a1); a1 = fmaf(q4[i+1].y, k1.y, a1);
            a1 = fmaf(q4[i+1].z, k1.z, a1); a1 = fmaf(q4[i+1].w, k1.w, a1);
            a2 = fmaf(q4[i+2].x, k2.x, a2); a2 = fmaf(q4[i+2].y, k2.y, a2);
            a2 = fmaf(q4[i+2].z, k2.z, a2); a2 = fmaf(q4[i+2].w, k2.w, a2);
            a3 = fmaf(q4[i+3].x, k3.x, a3); a3 = fmaf(q4[i+3].y, k3.y, a3);
            a3 = fmaf(q4[i+3].z, k3.z, a3); a3 = fmaf(q4[i+3].w, k3.w, a3);
        }
        float sc = ((a0 + a1) + (a2 + a3)) * scale;

        if (sc > m) {
            float alpha = __expf(m - sc);
            l *= alpha;
            #pragma unroll
            for (int i = 0; i < 16; i++) {
                o4[i].x *= alpha; o4[i].y *= alpha;
                o4[i].z *= alpha; o4[i].w *= alpha;
            }
            m = sc;
        }
        float p = __expf(sc - m);
        l += p;
        const float4* vrow = (const float4*)&Vs[s * DD];
        #pragma unroll
        for (int i = 0; i < 16; i++) {
            float4 vv = vrow[i];
            o4[i].x = fmaf(p, vv.x, o4[i].x);
            o4[i].y = fmaf(p, vv.y, o4[i].y);
            o4[i].z = fmaf(p, vv.z, o4[i].z);
            o4[i].w = fmaf(p, vv.w, o4[i].w);
        }
    }

    float inv = 1.f / l;
    int b = bh / HH, h = bh % HH;
    size_t obase = (size_t)(b * TT + t) * CC + h * DD;
    #pragma unroll
    for (int i = 0; i < 8; i++) {            // FIXED: 8 iterations cover all 64 elems
        float vals[8];
        #pragma unroll
        for (int j2 = 0; j2 < 2; j2++) {
            float4 o = o4[i*2 + j2];
            vals[j2*4+0] = o.x*inv; vals[j2*4+1] = o.y*inv;
            vals[j2*4+2] = o.z*inv; vals[j2*4+3] = o.w*inv;
        }
        __nv_bfloat16 hv[8], lv[8];
        #pragma unroll
        for (int j2 = 0; j2 < 8; j2++) {
            hv[j2] = __float2bfloat16(vals[j2]);
            lv[j2] = __float2bfloat16(vals[j2] - __bfloat162float(hv[j2]));
        }
        *(uint4*)(g_Athi + obase + i*8) = *(uint4*)hv;
        *(uint4*)(g_Atlo + obase + i*8) = *(uint4*)lv;
    }
}

// ---------------------------------------------------------------------------
extern "C" void kernel_launch(void* const* d_in, const int* in_sizes, int n_in,
                              void* d_out, int out_size) {
    const float* x  = (const float*)d_in[0];
    const float* Wq = (const float*)d_in[1];
    const float* Wk = (const float*)d_in[2];
    const float* Wv = (const float*)d_in[3];
    const float* Wp = (const float*)d_in[4];
    const float* bp = (const float*)d_in[5];
    float* out = (float*)d_out;

    // 1) splits / packs
    split_x<<<(BT*CC/8 + 255)/256, 256>>>(x);
    pack_wt_kernel<<<(NQKV*CC + 255)/256, 256>>>(Wq, Wk, Wv);
    split_wp<<<(CC*CC/8 + 255)/256, 256>>>(Wp);

    const int gsmem = 2 * 4 * TILE_B;  // 81920
    cudaFuncSetAttribute(gemm_tc<0>, cudaFuncAttributeMaxDynamicSharedMemorySize, gsmem);
    cudaFuncSetAttribute(gemm_tc<1>, cudaFuncAttributeMaxDynamicSharedMemorySize, gsmem);

    // 2) QKV projection GEMM -> q/k/v
    gemm_tc<0><<<dim3(NQKV/128, BT/128), 256, gsmem>>>(nullptr, nullptr);

    // 3) causal attention -> bf16 hi/lo att (fused split)
    const int asmem = 2 * TT * DD * (int)sizeof(float);  // 128 KB
    cudaFuncSetAttribute(attn_kernel, cudaFuncAttributeMaxDynamicSharedMemorySize, asmem);
    attn_kernel<<<BB*HH, 256, asmem>>>();

    // 4) output projection + bias
    gemm_tc<1><<<dim3(CC/128, BT/128), 256, gsmem>>>(bp, out);
}

// round 7
// speedup vs baseline: 2.8242x; 1.5815x over previous
#include <cuda_runtime.h>
#include <cuda_bf16.h>
#include <cstdint>

#define BB 64
#define TT 256
#define CC 384
#define HH 6
#define DD 64
#define BT (BB*TT)         // 16384
#define NQKV (3*HH*DD)     // 1152
#define PITCH 40           // bf16 elems per smem row (80B, conflict-free) - GEMM
#define TILE_B (128*PITCH*2)  // 10240 bytes per 128x32 tile

// attention smem layout (bytes). Q/K pitch 72 bf16 (144B), Vt pitch 264 bf16 (528B)
#define AQH 0
#define AQL 36864
#define AKH 73728
#define AKL 110592
#define AVH 147456
#define AVL 181248
#define ASZ 215040

// ---------------- static scratch ----------------
__device__ __align__(128) __nv_bfloat16 g_Xhi[(size_t)BT*CC],   g_Xlo[(size_t)BT*CC];
__device__ __align__(128) __nv_bfloat16 g_Wthi[(size_t)NQKV*CC], g_Wtlo[(size_t)NQKV*CC];
__device__ __align__(128) __nv_bfloat16 g_Athi[(size_t)BT*CC],  g_Atlo[(size_t)BT*CC];
__device__ __align__(128) __nv_bfloat16 g_Wphi[(size_t)CC*CC],  g_Wplo[(size_t)CC*CC];
__device__ __align__(128) __nv_bfloat16 g_Qh[(size_t)BB*HH*TT*DD], g_Ql[(size_t)BB*HH*TT*DD];
__device__ __align__(128) __nv_bfloat16 g_Kh[(size_t)BB*HH*TT*DD], g_Kl[(size_t)BB*HH*TT*DD];
__device__ __align__(128) __nv_bfloat16 g_Vth[(size_t)BB*HH*DD*TT], g_Vtl[(size_t)BB*HH*DD*TT];

// ---------------- helpers ----------------
__device__ __forceinline__ void ldgsts16(uint32_t s, const void* g) {
    asm volatile("cp.async.cg.shared.global [%0], [%1], 16;" :: "r"(s), "l"(g));
}
__device__ __forceinline__ void mma_bf16(float* c, const uint32_t* a, const uint32_t* b) {
    asm volatile("mma.sync.aligned.m16n8k16.row.col.f32.bf16.bf16.f32 "
                 "{%0,%1,%2,%3}, {%4,%5,%6,%7}, {%8,%9}, {%0,%1,%2,%3};"
                 : "+f"(c[0]), "+f"(c[1]), "+f"(c[2]), "+f"(c[3])
                 : "r"(a[0]), "r"(a[1]), "r"(a[2]), "r"(a[3]),
                   "r"(b[0]), "r"(b[1]));
}
__device__ __forceinline__ void split2(float x, float y, uint32_t& hi, uint32_t& lo) {
    __nv_bfloat16 hx = __float2bfloat16(x), hy = __float2bfloat16(y);
    __nv_bfloat16 lx = __float2bfloat16(x - __bfloat162float(hx));
    __nv_bfloat16 ly = __float2bfloat16(y - __bfloat162float(hy));
    uint16_t uhx = *(uint16_t*)&hx, uhy = *(uint16_t*)&hy;
    uint16_t ulx = *(uint16_t*)&lx, uly = *(uint16_t*)&ly;
    hi = (uint32_t)uhx | ((uint32_t)uhy << 16);
    lo = (uint32_t)ulx | ((uint32_t)uly << 16);
}

// ---------------- split / pack kernels ----------------
__global__ void split_x(const float* __restrict__ src) {
    int i = (blockIdx.x * blockDim.x + threadIdx.x) * 8;
    if (i >= BT*CC) return;
    float4 v0 = *(const float4*)(src + i);
    float4 v1 = *(const float4*)(src + i + 4);
    __nv_bfloat16 h[8], l[8];
    float vv[8] = {v0.x,v0.y,v0.z,v0.w,v1.x,v1.y,v1.z,v1.w};
    #pragma unroll
    for (int j = 0; j < 8; j++) {
        h[j] = __float2bfloat16(vv[j]);
        l[j] = __float2bfloat16(vv[j] - __bfloat162float(h[j]));
    }
    *(uint4*)(g_Xhi + i) = *(uint4*)h;
    *(uint4*)(g_Xlo + i) = *(uint4*)l;
}
__global__ void split_wp(const float* __restrict__ Wp) {
    int i = (blockIdx.x * blockDim.x + threadIdx.x) * 8;
    if (i >= CC*CC) return;
    float4 v0 = *(const float4*)(Wp + i);
    float4 v1 = *(const float4*)(Wp + i + 4);
    __nv_bfloat16 h[8], l[8];
    float vv[8] = {v0.x,v0.y,v0.z,v0.w,v1.x,v1.y,v1.z,v1.w};
    #pragma unroll
    for (int j = 0; j < 8; j++) {
        h[j] = __float2bfloat16(vv[j]);
        l[j] = __float2bfloat16(vv[j] - __bfloat162float(h[j]));
    }
    *(uint4*)(g_Wphi + i) = *(uint4*)h;
    *(uint4*)(g_Wplo + i) = *(uint4*)l;
}
__global__ void pack_wt_kernel(const float* __restrict__ Wq,
                               const float* __restrict__ Wk,
                               const float* __restrict__ Wv) {
    int idx = blockIdx.x * blockDim.x + threadIdx.x;
    if (idx >= NQKV * CC) return;
    int n = idx / CC, c = idx % CC;
    int proj = n / (HH * DD), r = n % (HH * DD);
    int h = r / DD, d = r % DD;
    const float* W = (proj == 0) ? Wq : (proj == 1) ? Wk : Wv;
    float v = W[((size_t)h * CC + c) * DD + d];
    __nv_bfloat16 hi = __float2bfloat16(v);
    g_Wthi[idx] = hi;
    g_Wtlo[idx] = __float2bfloat16(v - __bfloat162float(hi));
}

// ---------------------------------------------------------------------------
// HMMA GEMM: D[m][n] = sum_k A[m,k]*Bt[n,k], bf16 hi/lo 3-product, fp32 acc.
// MODE 0: A=Xsplit, B=Wtsplit, emit bf16 hi/lo Q,K[t][d] and Vt[d][t].
// MODE 1: A=Attsplit, B=Wpsplit, +bias -> fp32 out.
// ---------------------------------------------------------------------------
template<int MODE>
__global__ __launch_bounds__(256, 2) void gemm_tc(const float* __restrict__ bp,
                                                  float* __restrict__ outp) {
    extern __shared__ __align__(128) char sm[];
    const __nv_bfloat16* Ahi = (MODE == 0) ? g_Xhi  : g_Athi;
    const __nv_bfloat16* Alo = (MODE == 0) ? g_Xlo  : g_Atlo;
    const __nv_bfloat16* Bhi = (MODE == 0) ? g_Wthi : g_Wphi;
    const __nv_bfloat16* Blo = (MODE == 0) ? g_Wtlo : g_Wplo;

    const int tid = threadIdx.x, lane = tid & 31, wid = tid >> 5;
    const int wm = wid & 3, wn = wid >> 2;
    const int lr = lane >> 2, lc = lane & 3;
    const int row0 = blockIdx.y * 128, col0 = blockIdx.x * 128;

    const int r0 = tid >> 2, sg = tid & 3;
    const uint32_t sbase = (uint32_t)__cvta_generic_to_shared(sm);

    auto load_stage = [&](int buf, int k0) {
        uint32_t st = sbase + buf * 4 * TILE_B;
        #pragma unroll
        for (int rep = 0; rep < 2; rep++) {
            int row = r0 + rep * 64;
            uint32_t so = row * (PITCH * 2) + sg * 16;
            size_t goA = (size_t)(row0 + row) * CC + k0 + sg * 8;
            size_t goB = (size_t)(col0 + row) * CC + k0 + sg * 8;
            ldgsts16(st + 0*TILE_B + so, Ahi + goA);
            ldgsts16(st + 1*TILE_B + so, Alo + goA);
            ldgsts16(st + 2*TILE_B + so, Bhi + goB);
            ldgsts16(st + 3*TILE_B + so, Blo + goB);
        }
    };

    float acc[2][8][4];
    #pragma unroll
    for (int i = 0; i < 2; i++)
        #pragma unroll
        for (int j = 0; j < 8; j++)
            #pragma unroll
            for (int r = 0; r < 4; r++) acc[i][j][r] = 0.f;

    load_stage(0, 0);
    asm volatile("cp.async.commit_group;" ::: "memory");

    for (int kc = 0; kc < 12; kc++) {
        int buf = kc & 1;
        if (kc < 11) {
            load_stage(buf ^ 1, (kc + 1) * 32);
            asm volatile("cp.async.commit_group;" ::: "memory");
            asm volatile("cp.async.wait_group 1;" ::: "memory");
        } else {
            asm volatile("cp.async.wait_group 0;" ::: "memory");
        }
        __syncthreads();

        const char* base = sm + buf * 4 * TILE_B;
        #pragma unroll
        for (int ks = 0; ks < 2; ks++) {
            const int kb = ks * 16;
            uint32_t ah[2][4], al[2][4];
            #pragma unroll
            for (int i = 0; i < 2; i++) {
                const char* p = base + ((wm*32 + i*16 + lr) * PITCH + kb + lc*2) * 2;
                ah[i][0] = *(const uint32_t*)(p);
                ah[i][1] = *(const uint32_t*)(p + 8 * PITCH * 2);
                ah[i][2] = *(const uint32_t*)(p + 16);
                ah[i][3] = *(const uint32_t*)(p + 8 * PITCH * 2 + 16);
                const char* q = p + TILE_B;
                al[i][0] = *(const uint32_t*)(q);
                al[i][1] = *(const uint32_t*)(q + 8 * PITCH * 2);
                al[i][2] = *(const uint32_t*)(q + 16);
                al[i][3] = *(const uint32_t*)(q + 8 * PITCH * 2 + 16);
            }
            #pragma unroll
            for (int j = 0; j < 8; j++) {
                const char* p = base + 2*TILE_B +
                                ((wn*64 + j*8 + lr) * PITCH + kb + lc*2) * 2;
                uint32_t bh[2], bl[2];
                bh[0] = *(const uint32_t*)(p);
                bh[1] = *(const uint32_t*)(p + 16);
                bl[0] = *(const uint32_t*)(p + TILE_B);
                bl[1] = *(const uint32_t*)(p + TILE_B + 16);
                #pragma unroll
                for (int i = 0; i < 2; i++) {
                    mma_bf16(acc[i][j], ah[i], bh);
                    mma_bf16(acc[i][j], ah[i], bl);
                    mma_bf16(acc[i][j], al[i], bh);
                }
            }
        }
        __syncthreads();
    }

    // epilogue
    #pragma unroll
    for (int i = 0; i < 2; i++) {
        int m0 = row0 + wm*32 + i*16 + lr;
        #pragma unroll
        for (int j = 0; j < 8; j++) {
            int nn = col0 + wn*64 + j*8 + lc*2;
            if (MODE == 0) {
                int proj = nn / (HH*DD);
                int rem  = nn % (HH*DD);
                int h = rem / DD, d = rem % DD;
                int b = m0 / TT, t = m0 % TT;
                int bh = b*HH + h;
                if (proj < 2) {
                    __nv_bfloat16* dh = (proj == 0) ? g_Qh : g_Kh;
                    __nv_bfloat16* dl = (proj == 0) ? g_Ql : g_Kl;
                    uint32_t h01, l01, h23, l23;
                    split2(acc[i][j][0], acc[i][j][1], h01, l01);
                    split2(acc[i][j][2], acc[i][j][3], h23, l23);
                    size_t o = ((size_t)bh*TT + t)*DD + d;
                    *(uint32_t*)(dh + o) = h01;            *(uint32_t*)(dl + o) = l01;
                    *(uint32_t*)(dh + o + 8*DD) = h23;     *(uint32_t*)(dl + o + 8*DD) = l23;
                } else {
                    // V transposed: [bh][d][t]
                    size_t o = ((size_t)bh*DD + d)*TT + t;
                    float v00 = acc[i][j][0], v01 = acc[i][j][1];
                    float v10 = acc[i][j][2], v11 = acc[i][j][3];
                    __nv_bfloat16 hv, lv;
                    hv = __float2bfloat16(v00); lv = __float2bfloat16(v00 - __bfloat162float(hv));
                    g_Vth[o] = hv;              g_Vtl[o] = lv;
                    hv = __float2bfloat16(v01); lv = __float2bfloat16(v01 - __bfloat162float(hv));
                    g_Vth[o + TT] = hv;         g_Vtl[o + TT] = lv;
                    hv = __float2bfloat16(v10); lv = __float2bfloat16(v10 - __bfloat162float(hv));
                    g_Vth[o + 8] = hv;          g_Vtl[o + 8] = lv;
                    hv = __float2bfloat16(v11); lv = __float2bfloat16(v11 - __bfloat162float(hv));
                    g_Vth[o + TT + 8] = hv;     g_Vtl[o + TT + 8] = lv;
                }
            } else {
                float2 bb = *(const float2*)(bp + nn);
                *(float2*)(outp + (size_t)m0 * CC + nn) =
                    make_float2(acc[i][j][0] + bb.x, acc[i][j][1] + bb.y);
                *(float2*)(outp + (size_t)(m0 + 8) * CC + nn) =
                    make_float2(acc[i][j][2] + bb.x, acc[i][j][3] + bb.y);
            }
        }
    }
}

// ---------------------------------------------------------------------------
// HMMA flash attention: 1 CTA per (b,h). 8 warps x 32 query rows.
// Q,K [t][d] pitch 72, Vt [d][s] pitch 264, all bf16 hi/lo in smem.
// Per-warp causal chunk loop (64 keys/chunk), no barriers in main loop.
// ---------------------------------------------------------------------------
__global__ __launch_bounds__(256, 1) void attn_flash() {
    extern __shared__ __align__(128) char sma[];
    const int bh = blockIdx.x;
    const int tid = threadIdx.x, lane = tid & 31, w = tid >> 5;
    const int lr = lane >> 2, lc = lane & 3;
    const uint32_t sb = (uint32_t)__cvta_generic_to_shared(sma);

    // ---- stage Q,K (4 tensors, 256 rows x 8 chunks) and Vt (2 tensors, 64 x 32)
    {
        const __nv_bfloat16* qh = g_Qh + (size_t)bh*TT*DD;
        const __nv_bfloat16* ql = g_Ql + (size_t)bh*TT*DD;
        const __nv_bfloat16* kh = g_Kh + (size_t)bh*TT*DD;
        const __nv_bfloat16* kl = g_Kl + (size_t)bh*TT*DD;
        for (int i = tid; i < 2048; i += 256) {
            int row = i >> 3, ch = i & 7;
            uint32_t so = row*144 + ch*16;
            size_t  go = (size_t)row*DD + ch*8;
            ldgsts16(sb + AQH + so, qh + go);
            ldgsts16(sb + AQL + so, ql + go);
            ldgsts16(sb + AKH + so, kh + go);
            ldgsts16(sb + AKL + so, kl + go);
        }
        const __nv_bfloat16* vh = g_Vth + (size_t)bh*DD*TT;
        const __nv_bfloat16* vl = g_Vtl + (size_t)bh*DD*TT;
        for (int i = tid; i < 2048; i += 256) {
            int row = i >> 5, ch = i & 31;
            uint32_t so = row*528 + ch*16;
            size_t  go = (size_t)row*TT + ch*8;
            ldgsts16(sb + AVH + so, vh + go);
            ldgsts16(sb + AVL + so, vl + go);
        }
        asm volatile("cp.async.commit_group;" ::: "memory");
        asm volatile("cp.async.wait_group 0;" ::: "memory");
        __syncthreads();
    }

    const int t0 = w * 32;
    float O[2][8][4];
    #pragma unroll
    for (int mt = 0; mt < 2; mt++)
        #pragma unroll
        for (int j = 0; j < 8; j++)
            #pragma unroll
            for (int r = 0; r < 4; r++) O[mt][j][r] = 0.f;
    float mrow[2][2] = {{-1e30f,-1e30f},{-1e30f,-1e30f}};
    float lrow[2][2] = {{0.f,0.f},{0.f,0.f}};

    const int nch = w/2 + 1;
    for (int c = 0; c < nch; c++) {
        const int s0 = c * 64;
        float S[2][8][4];
        #pragma unroll
        for (int mt = 0; mt < 2; mt++)
            #pragma unroll
            for (int n = 0; n < 8; n++)
                #pragma unroll
                for (int r = 0; r < 4; r++) S[mt][n][r] = 0.f;

        // ---- S = Q K^T (3-product hi/lo)
        #pragma unroll
        for (int ks = 0; ks < 4; ks++) {
            uint32_t ah[2][4], al[2][4];
            #pragma unroll
            for (int mt = 0; mt < 2; mt++) {
                uint32_t off = (uint32_t)(t0 + mt*16 + lr)*144 + (ks*16 + lc*2)*2;
                ah[mt][0] = *(const uint32_t*)(sma + AQH + off);
                ah[mt][1] = *(const uint32_t*)(sma + AQH + off + 8*144);
                ah[mt][2] = *(const uint32_t*)(sma + AQH + off + 16);
                ah[mt][3] = *(const uint32_t*)(sma + AQH + off + 8*144 + 16);
                al[mt][0] = *(const uint32_t*)(sma + AQL + off);
                al[mt][1] = *(const uint32_t*)(sma + AQL + off + 8*144);
                al[mt][2] = *(const uint32_t*)(sma + AQL + off + 16);
                al[mt][3] = *(const uint32_t*)(sma + AQL + off + 8*144 + 16);
            }
            #pragma unroll
            for (int n = 0; n < 8; n++) {
                uint32_t off = (uint32_t)(s0 + n*8 + lr)*144 + (ks*16 + lc*2)*2;
                uint32_t kbh[2], kbl[2];
                kbh[0] = *(const uint32_t*)(sma + AKH + off);
                kbh[1] = *(const uint32_t*)(sma + AKH + off + 16);
                kbl[0] = *(const uint32_t*)(sma + AKL + off);
                kbl[1] = *(const uint32_t*)(sma + AKL + off + 16);
                #pragma unroll
                for (int mt = 0; mt < 2; mt++) {
                    mma_bf16(S[mt][n], ah[mt], kbh);
                    mma_bf16(S[mt][n], ah[mt], kbl);
                    mma_bf16(S[mt][n], al[mt], kbh);
                }
            }
        }

        // ---- scale + causal mask (diagonal chunk only)
        const bool diag = (c == w/2);
        #pragma unroll
        for (int mt = 0; mt < 2; mt++) {
            int trow = t0 + mt*16 + lr;
            #pragma unroll
            for (int n = 0; n < 8; n++) {
                int scol = s0 + n*8 + lc*2;
                S[mt][n][0] *= 0.125f; S[mt][n][1] *= 0.125f;
                S[mt][n][2] *= 0.125f; S[mt][n][3] *= 0.125f;
                if (diag) {
                    if (scol     > trow)     S[mt][n][0] = -1e30f;
                    if (scol + 1 > trow)     S[mt][n][1] = -1e30f;
                    if (scol     > trow + 8) S[mt][n][2] = -1e30f;
                    if (scol + 1 > trow + 8) S[mt][n][3] = -1e30f;
                }
            }
        }

        // ---- online softmax per row (rows lr / lr+8 per mtile)
        #pragma unroll
        for (int mt = 0; mt < 2; mt++) {
            #pragma unroll
            for (int rg = 0; rg < 2; rg++) {
                float cm = -1e30f;
                #pragma unroll
                for (int n = 0; n < 8; n++) {
                    cm = fmaxf(cm, S[mt][n][rg*2]);
                    cm = fmaxf(cm, S[mt][n][rg*2+1]);
                }
                cm = fmaxf(cm, __shfl_xor_sync(0xffffffffu, cm, 1));
                cm = fmaxf(cm, __shfl_xor_sync(0xffffffffu, cm, 2));
                float mold = mrow[mt][rg];
                float mn = fmaxf(mold, cm);
                float alpha = __expf(mold - mn);
                mrow[mt][rg] = mn;
                float ls = 0.f;
                #pragma unroll
                for (int n = 0; n < 8; n++) {
                    float p0 = __expf(S[mt][n][rg*2]   - mn);
                    float p1 = __expf(S[mt][n][rg*2+1] - mn);
                    S[mt][n][rg*2] = p0; S[mt][n][rg*2+1] = p1;
                    ls += p0 + p1;
                }
                lrow[mt][rg] = lrow[mt][rg]*alpha + ls;
                #pragma unroll
                for (int j = 0; j < 8; j++) {
                    O[mt][j][rg*2]   *= alpha;
                    O[mt][j][rg*2+1] *= alpha;
                }
            }
        }

        // ---- O += P V (P hi/lo from S regs; C-frag == A-frag mapping)
        #pragma unroll
        for (int ks2 = 0; ks2 < 4; ks2++) {
            uint32_t ph[2][4], pl[2][4];
            #pragma unroll
            for (int mt = 0; mt < 2; mt++) {
                split2(S[mt][2*ks2][0],   S[mt][2*ks2][1],   ph[mt][0], pl[mt][0]);
                split2(S[mt][2*ks2][2],   S[mt][2*ks2][3],   ph[mt][1], pl[mt][1]);
                split2(S[mt][2*ks2+1][0], S[mt][2*ks2+1][1], ph[mt][2], pl[mt][2]);
                split2(S[mt][2*ks2+1][2], S[mt][2*ks2+1][3], ph[mt][3], pl[mt][3]);
            }
            #pragma unroll
            for (int j = 0; j < 8; j++) {
                uint32_t off = (uint32_t)(j*8 + lr)*528 + (s0 + ks2*16 + lc*2)*2;
                uint32_t vbh[2], vbl[2];
                vbh[0] = *(const uint32_t*)(sma + AVH + off);
                vbh[1] = *(const uint32_t*)(sma + AVH + off + 16);
                vbl[0] = *(const uint32_t*)(sma + AVL + off);
                vbl[1] = *(const uint32_t*)(sma + AVL + off + 16);
                #pragma unroll
                for (int mt = 0; mt < 2; mt++) {
                    mma_bf16(O[mt][j], ph[mt], vbh);
                    mma_bf16(O[mt][j], ph[mt], vbl);
                    mma_bf16(O[mt][j], pl[mt], vbh);
                }
            }
        }
    }

    // ---- finalize: 1/l, write bf16 hi/lo att [b, t, h*D + d]
    float linv[2][2];
    #pragma unroll
    for (int mt = 0; mt < 2; mt++)
        #pragma unroll
        for (int rg = 0; rg < 2; rg++) {
            float lf = lrow[mt][rg];
            lf += __shfl_xor_sync(0xffffffffu, lf, 1);
            lf += __shfl_xor_sync(0xffffffffu, lf, 2);
            linv[mt][rg] = 1.f / lf;
        }
    const int b = bh / HH, h = bh % HH;
    #pragma unroll
    for (int mt = 0; mt < 2; mt++) {
        int r0 = t0 + mt*16 + lr;
        #pragma unroll
        for (int j = 0; j < 8; j++) {
            int d = j*8 + lc*2;
            uint32_t hi, lo;
            size_t o0 = ((size_t)(b*TT + r0))*CC + h*DD + d;
            split2(O[mt][j][0]*linv[mt][0], O[mt][j][1]*linv[mt][0], hi, lo);
            *(uint32_t*)(g_Athi + o0) = hi;  *(uint32_t*)(g_Atlo + o0) = lo;
            size_t o1 = ((size_t)(b*TT + r0 + 8))*CC + h*DD + d;
            split2(O[mt][j][2]*linv[mt][1], O[mt][j][3]*linv[mt][1], hi, lo);
            *(uint32_t*)(g_Athi + o1) = hi;  *(uint32_t*)(g_Atlo + o1) = lo;
        }
    }
}

// ---------------------------------------------------------------------------
extern "C" void kernel_launch(void* const* d_in, const int* in_sizes, int n_in,
                              void* d_out, int out_size) {
    const float* x  = (const float*)d_in[0];
    const float* Wq = (const float*)d_in[1];
    const float* Wk = (const float*)d_in[2];
    const float* Wv = (const float*)d_in[3];
    const float* Wp = (const float*)d_in[4];
    const float* bp = (const float*)d_in[5];
    float* out = (float*)d_out;

    // 1) splits / packs
    split_x<<<(BT*CC/8 + 255)/256, 256>>>(x);
    pack_wt_kernel<<<(NQKV*CC + 255)/256, 256>>>(Wq, Wk, Wv);
    split_wp<<<(CC*CC/8 + 255)/256, 256>>>(Wp);

    const int gsmem = 2 * 4 * TILE_B;  // 81920
    cudaFuncSetAttribute(gemm_tc<0>, cudaFuncAttributeMaxDynamicSharedMemorySize, gsmem);
    cudaFuncSetAttribute(gemm_tc<1>, cudaFuncAttributeMaxDynamicSharedMemorySize, gsmem);

    // 2) QKV projection GEMM -> bf16 hi/lo Q,K,Vt
    gemm_tc<0><<<dim3(NQKV/128, BT/128), 256, gsmem>>>(nullptr, nullptr);

    // 3) HMMA flash attention -> bf16 hi/lo att
    cudaFuncSetAttribute(attn_flash, cudaFuncAttributeMaxDynamicSharedMemorySize, ASZ);
    attn_flash<<<BB*HH, 256, ASZ>>>();

    // 4) output projection + bias
    gemm_tc<1><<<dim3(CC/128, BT/128), 256, gsmem>>>(bp, out);
}

// round 8
// speedup vs baseline: 2.9279x; 1.0367x over previous
#include <cuda_runtime.h>
#include <cuda_bf16.h>
#include <cstdint>

#define BB 64
#define TT 256
#define CC 384
#define HH 6
#define DD 64
#define BT (BB*TT)         // 16384
#define NQKV (3*HH*DD)     // 1152
#define PITCH 40           // bf16 elems per smem row (80B, conflict-free) - GEMM
#define TILE_B (128*PITCH*2)  // 10240 bytes per 128x32 tile

// attention smem layout (bytes). Q/K pitch 72 bf16 (144B), Vt pitch 264 bf16 (528B)
#define AQH 0
#define AQL 36864
#define AKH 73728
#define AKL 110592
#define AVH 147456
#define AVL 181248
#define ASZ 215040

// ---------------- static scratch ----------------
__device__ __align__(128) __nv_bfloat16 g_Xhi[(size_t)BT*CC],   g_Xlo[(size_t)BT*CC];
__device__ __align__(128) __nv_bfloat16 g_Wthi[(size_t)NQKV*CC], g_Wtlo[(size_t)NQKV*CC];
__device__ __align__(128) __nv_bfloat16 g_Athi[(size_t)BT*CC],  g_Atlo[(size_t)BT*CC];
__device__ __align__(128) __nv_bfloat16 g_Wphi[(size_t)CC*CC],  g_Wplo[(size_t)CC*CC];
__device__ __align__(128) __nv_bfloat16 g_Qh[(size_t)BB*HH*TT*DD], g_Ql[(size_t)BB*HH*TT*DD];
__device__ __align__(128) __nv_bfloat16 g_Kh[(size_t)BB*HH*TT*DD], g_Kl[(size_t)BB*HH*TT*DD];
__device__ __align__(128) __nv_bfloat16 g_Vth[(size_t)BB*HH*DD*TT], g_Vtl[(size_t)BB*HH*DD*TT];

// ---------------- helpers ----------------
__device__ __forceinline__ void ldgsts16(uint32_t s, const void* g) {
    asm volatile("cp.async.cg.shared.global [%0], [%1], 16;" :: "r"(s), "l"(g));
}
__device__ __forceinline__ void mma_bf16(float* c, const uint32_t* a, const uint32_t* b) {
    asm volatile("mma.sync.aligned.m16n8k16.row.col.f32.bf16.bf16.f32 "
                 "{%0,%1,%2,%3}, {%4,%5,%6,%7}, {%8,%9}, {%0,%1,%2,%3};"
                 : "+f"(c[0]), "+f"(c[1]), "+f"(c[2]), "+f"(c[3])
                 : "r"(a[0]), "r"(a[1]), "r"(a[2]), "r"(a[3]),
                   "r"(b[0]), "r"(b[1]));
}
__device__ __forceinline__ void ldm_x4(uint32_t* r, uint32_t addr) {
    asm volatile("ldmatrix.sync.aligned.m8n8.x4.shared.b16 {%0,%1,%2,%3}, [%4];"
                 : "=r"(r[0]), "=r"(r[1]), "=r"(r[2]), "=r"(r[3]) : "r"(addr));
}
__device__ __forceinline__ void split2(float x, float y, uint32_t& hi, uint32_t& lo) {
    __nv_bfloat16 hx = __float2bfloat16(x), hy = __float2bfloat16(y);
    __nv_bfloat16 lx = __float2bfloat16(x - __bfloat162float(hx));
    __nv_bfloat16 ly = __float2bfloat16(y - __bfloat162float(hy));
    uint16_t uhx = *(uint16_t*)&hx, uhy = *(uint16_t*)&hy;
    uint16_t ulx = *(uint16_t*)&lx, uly = *(uint16_t*)&ly;
    hi = (uint32_t)uhx | ((uint32_t)uhy << 16);
    lo = (uint32_t)ulx | ((uint32_t)uly << 16);
}

// ---------------- split / pack kernels ----------------
__global__ void split_x(const float* __restrict__ src) {
    int i = (blockIdx.x * blockDim.x + threadIdx.x) * 8;
    if (i >= BT*CC) return;
    float4 v0 = *(const float4*)(src + i);
    float4 v1 = *(const float4*)(src + i + 4);
    __nv_bfloat16 h[8], l[8];
    float vv[8] = {v0.x,v0.y,v0.z,v0.w,v1.x,v1.y,v1.z,v1.w};
    #pragma unroll
    for (int j = 0; j < 8; j++) {
        h[j] = __float2bfloat16(vv[j]);
        l[j] = __float2bfloat16(vv[j] - __bfloat162float(h[j]));
    }
    *(uint4*)(g_Xhi + i) = *(uint4*)h;
    *(uint4*)(g_Xlo + i) = *(uint4*)l;
}
__global__ void split_wp(const float* __restrict__ Wp) {
    int i = (blockIdx.x * blockDim.x + threadIdx.x) * 8;
    if (i >= CC*CC) return;
    float4 v0 = *(const float4*)(Wp + i);
    float4 v1 = *(const float4*)(Wp + i + 4);
    __nv_bfloat16 h[8], l[8];
    float vv[8] = {v0.x,v0.y,v0.z,v0.w,v1.x,v1.y,v1.z,v1.w};
    #pragma unroll
    for (int j = 0; j < 8; j++) {
        h[j] = __float2bfloat16(vv[j]);
        l[j] = __float2bfloat16(vv[j] - __bfloat162float(h[j]));
    }
    *(uint4*)(g_Wphi + i) = *(uint4*)h;
    *(uint4*)(g_Wplo + i) = *(uint4*)l;
}
__global__ void pack_wt_kernel(const float* __restrict__ Wq,
                               const float* __restrict__ Wk,
                               const float* __restrict__ Wv) {
    int idx = blockIdx.x * blockDim.x + threadIdx.x;
    if (idx >= NQKV * CC) return;
    int n = idx / CC, c = idx % CC;
    int proj = n / (HH * DD), r = n % (HH * DD);
    int h = r / DD, d = r % DD;
    const float* W = (proj == 0) ? Wq : (proj == 1) ? Wk : Wv;
    float v = W[((size_t)h * CC + c) * DD + d];
    __nv_bfloat16 hi = __float2bfloat16(v);
    g_Wthi[idx] = hi;
    g_Wtlo[idx] = __float2bfloat16(v - __bfloat162float(hi));
}

// ---------------------------------------------------------------------------
// HMMA GEMM with ldmatrix fragment loads.
// MODE 0: A=Xsplit, B=Wtsplit, emit bf16 hi/lo Q,K[t][d] and Vt[d][t].
// MODE 1: A=Attsplit, B=Wpsplit, +bias -> fp32 out.
// ---------------------------------------------------------------------------
template<int MODE>
__global__ __launch_bounds__(256, 2) void gemm_tc(const float* __restrict__ bp,
                                                  float* __restrict__ outp) {
    extern __shared__ __align__(128) char sm[];
    const __nv_bfloat16* Ahi = (MODE == 0) ? g_Xhi  : g_Athi;
    const __nv_bfloat16* Alo = (MODE == 0) ? g_Xlo  : g_Atlo;
    const __nv_bfloat16* Bhi = (MODE == 0) ? g_Wthi : g_Wphi;
    const __nv_bfloat16* Blo = (MODE == 0) ? g_Wtlo : g_Wplo;

    const int tid = threadIdx.x, lane = tid & 31, wid = tid >> 5;
    const int wm = wid & 3, wn = wid >> 2;
    const int lr = lane >> 2, lc = lane & 3;
    const int row0 = blockIdx.y * 128, col0 = blockIdx.x * 128;

    const int r0 = tid >> 2, sg = tid & 3;
    const uint32_t sbase = (uint32_t)__cvta_generic_to_shared(sm);

    // ldmatrix per-lane element offsets (in bf16 elems, within a tile)
    // A x4: lanes 0-15 -> rows 0..15 @k0, lanes 16-31 -> rows 0..15 @k+8
    uint32_t aoff[2];
    #pragma unroll
    for (int mt = 0; mt < 2; mt++)
        aoff[mt] = (uint32_t)(wm*32 + mt*16 + (lane & 15)) * PITCH + ((lane >> 4) & 1) * 8;
    // B x4 (2 n-tiles): n = jj*16 + ((lane>>4)&1)*8 + (lane&7); k += ((lane>>3)&1)*8
    uint32_t boff[4];
    #pragma unroll
    for (int jj = 0; jj < 4; jj++)
        boff[jj] = (uint32_t)(wn*64 + jj*16 + ((lane >> 4) & 1)*8 + (lane & 7)) * PITCH
                   + ((lane >> 3) & 1) * 8;

    auto load_stage = [&](int buf, int k0) {
        uint32_t st = sbase + buf * 4 * TILE_B;
        #pragma unroll
        for (int rep = 0; rep < 2; rep++) {
            int row = r0 + rep * 64;
            uint32_t so = row * (PITCH * 2) + sg * 16;
            size_t goA = (size_t)(row0 + row) * CC + k0 + sg * 8;
            size_t goB = (size_t)(col0 + row) * CC + k0 + sg * 8;
            ldgsts16(st + 0*TILE_B + so, Ahi + goA);
            ldgsts16(st + 1*TILE_B + so, Alo + goA);
            ldgsts16(st + 2*TILE_B + so, Bhi + goB);
            ldgsts16(st + 3*TILE_B + so, Blo + goB);
        }
    };

    float acc[2][8][4];
    #pragma unroll
    for (int i = 0; i < 2; i++)
        #pragma unroll
        for (int j = 0; j < 8; j++)
            #pragma unroll
            for (int r = 0; r < 4; r++) acc[i][j][r] = 0.f;

    load_stage(0, 0);
    asm volatile("cp.async.commit_group;" ::: "memory");

    for (int kc = 0; kc < 12; kc++) {
        int buf = kc & 1;
        if (kc < 11) {
            load_stage(buf ^ 1, (kc + 1) * 32);
            asm volatile("cp.async.commit_group;" ::: "memory");
            asm volatile("cp.async.wait_group 1;" ::: "memory");
        } else {
            asm volatile("cp.async.wait_group 0;" ::: "memory");
        }
        __syncthreads();

        const uint32_t sbuf = sbase + buf * 4 * TILE_B;
        #pragma unroll
        for (int ks = 0; ks < 2; ks++) {
            const uint32_t kb = ks * 16;
            uint32_t ah[2][4], al[2][4];
            #pragma unroll
            for (int mt = 0; mt < 2; mt++) {
                uint32_t ad = sbuf + (aoff[mt] + kb) * 2;
                ldm_x4(ah[mt], ad);
                ldm_x4(al[mt], ad + TILE_B);
            }
            #pragma unroll
            for (int jj = 0; jj < 4; jj++) {
                uint32_t bd = sbuf + 2*TILE_B + (boff[jj] + kb) * 2;
                uint32_t bh4[4], bl4[4];
                ldm_x4(bh4, bd);
                ldm_x4(bl4, bd + TILE_B);
                #pragma unroll
                for (int mt = 0; mt < 2; mt++) {
                    mma_bf16(acc[mt][2*jj],   ah[mt], bh4);
                    mma_bf16(acc[mt][2*jj],   ah[mt], bl4);
                    mma_bf16(acc[mt][2*jj],   al[mt], bh4);
                    mma_bf16(acc[mt][2*jj+1], ah[mt], bh4 + 2);
                    mma_bf16(acc[mt][2*jj+1], ah[mt], bl4 + 2);
                    mma_bf16(acc[mt][2*jj+1], al[mt], bh4 + 2);
                }
            }
        }
        __syncthreads();
    }

    // epilogue
    #pragma unroll
    for (int i = 0; i < 2; i++) {
        int m0 = row0 + wm*32 + i*16 + lr;
        #pragma unroll
        for (int j = 0; j < 8; j++) {
            int nn = col0 + wn*64 + j*8 + lc*2;
            if (MODE == 0) {
                int proj = nn / (HH*DD);
                int rem  = nn % (HH*DD);
                int h = rem / DD, d = rem % DD;
                int b = m0 / TT, t = m0 % TT;
                int bh = b*HH + h;
                if (proj < 2) {
                    __nv_bfloat16* dh = (proj == 0) ? g_Qh : g_Kh;
                    __nv_bfloat16* dl = (proj == 0) ? g_Ql : g_Kl;
                    uint32_t h01, l01, h23, l23;
                    split2(acc[i][j][0], acc[i][j][1], h01, l01);
                    split2(acc[i][j][2], acc[i][j][3], h23, l23);
                    size_t o = ((size_t)bh*TT + t)*DD + d;
                    *(uint32_t*)(dh + o) = h01;            *(uint32_t*)(dl + o) = l01;
                    *(uint32_t*)(dh + o + 8*DD) = h23;     *(uint32_t*)(dl + o + 8*DD) = l23;
                } else {
                    size_t o = ((size_t)bh*DD + d)*TT + t;
                    float v00 = acc[i][j][0], v01 = acc[i][j][1];
                    float v10 = acc[i][j][2], v11 = acc[i][j][3];
                    __nv_bfloat16 hv, lv;
                    hv = __float2bfloat16(v00); lv = __float2bfloat16(v00 - __bfloat162float(hv));
                    g_Vth[o] = hv;              g_Vtl[o] = lv;
                    hv = __float2bfloat16(v01); lv = __float2bfloat16(v01 - __bfloat162float(hv));
                    g_Vth[o + TT] = hv;         g_Vtl[o + TT] = lv;
                    hv = __float2bfloat16(v10); lv = __float2bfloat16(v10 - __bfloat162float(hv));
                    g_Vth[o + 8] = hv;          g_Vtl[o + 8] = lv;
                    hv = __float2bfloat16(v11); lv = __float2bfloat16(v11 - __bfloat162float(hv));
                    g_Vth[o + TT + 8] = hv;     g_Vtl[o + TT + 8] = lv;
                }
            } else {
                float2 bb = *(const float2*)(bp + nn);
                *(float2*)(outp + (size_t)m0 * CC + nn) =
                    make_float2(acc[i][j][0] + bb.x, acc[i][j][1] + bb.y);
                *(float2*)(outp + (size_t)(m0 + 8) * CC + nn) =
                    make_float2(acc[i][j][2] + bb.x, acc[i][j][3] + bb.y);
            }
        }
    }
}

// ---------------------------------------------------------------------------
// HMMA flash attention: 1 CTA per (b,h). 8 warps x 32 query rows. (unchanged)
// ---------------------------------------------------------------------------
__global__ __launch_bounds__(256, 1) void attn_flash() {
    extern __shared__ __align__(128) char sma[];
    const int bh = blockIdx.x;
    const int tid = threadIdx.x, lane = tid & 31, w = tid >> 5;
    const int lr = lane >> 2, lc = lane & 3;
    const uint32_t sb = (uint32_t)__cvta_generic_to_shared(sma);

    {
        const __nv_bfloat16* qh = g_Qh + (size_t)bh*TT*DD;
        const __nv_bfloat16* ql = g_Ql + (size_t)bh*TT*DD;
        const __nv_bfloat16* kh = g_Kh + (size_t)bh*TT*DD;
        const __nv_bfloat16* kl = g_Kl + (size_t)bh*TT*DD;
        for (int i = tid; i < 2048; i += 256) {
            int row = i >> 3, ch = i & 7;
            uint32_t so = row*144 + ch*16;
            size_t  go = (size_t)row*DD + ch*8;
            ldgsts16(sb + AQH + so, qh + go);
            ldgsts16(sb + AQL + so, ql + go);
            ldgsts16(sb + AKH + so, kh + go);
            ldgsts16(sb + AKL + so, kl + go);
        }
        const __nv_bfloat16* vh = g_Vth + (size_t)bh*DD*TT;
        const __nv_bfloat16* vl = g_Vtl + (size_t)bh*DD*TT;
        for (int i = tid; i < 2048; i += 256) {
            int row = i >> 5, ch = i & 31;
            uint32_t so = row*528 + ch*16;
            size_t  go = (size_t)row*TT + ch*8;
            ldgsts16(sb + AVH + so, vh + go);
            ldgsts16(sb + AVL + so, vl + go);
        }
        asm volatile("cp.async.commit_group;" ::: "memory");
        asm volatile("cp.async.wait_group 0;" ::: "memory");
        __syncthreads();
    }

    const int t0 = w * 32;
    float O[2][8][4];
    #pragma unroll
    for (int mt = 0; mt < 2; mt++)
        #pragma unroll
        for (int j = 0; j < 8; j++)
            #pragma unroll
            for (int r = 0; r < 4; r++) O[mt][j][r] = 0.f;
    float mrow[2][2] = {{-1e30f,-1e30f},{-1e30f,-1e30f}};
    float lrow[2][2] = {{0.f,0.f},{0.f,0.f}};

    const int nch = w/2 + 1;
    for (int c = 0; c < nch; c++) {
        const int s0 = c * 64;
        float S[2][8][4];
        #pragma unroll
        for (int mt = 0; mt < 2; mt++)
            #pragma unroll
            for (int n = 0; n < 8; n++)
                #pragma unroll
                for (int r = 0; r < 4; r++) S[mt][n][r] = 0.f;

        #pragma unroll
        for (int ks = 0; ks < 4; ks++) {
            uint32_t ah[2][4], al[2][4];
            #pragma unroll
            for (int mt = 0; mt < 2; mt++) {
                uint32_t off = (uint32_t)(t0 + mt*16 + lr)*144 + (ks*16 + lc*2)*2;
                ah[mt][0] = *(const uint32_t*)(sma + AQH + off);
                ah[mt][1] = *(const uint32_t*)(sma + AQH + off + 8*144);
                ah[mt][2] = *(const uint32_t*)(sma + AQH + off + 16);
                ah[mt][3] = *(const uint32_t*)(sma + AQH + off + 8*144 + 16);
                al[mt][0] = *(const uint32_t*)(sma + AQL + off);
                al[mt][1] = *(const uint32_t*)(sma + AQL + off + 8*144);
                al[mt][2] = *(const uint32_t*)(sma + AQL + off + 16);
                al[mt][3] = *(const uint32_t*)(sma + AQL + off + 8*144 + 16);
            }
            #pragma unroll
            for (int n = 0; n < 8; n++) {
                uint32_t off = (uint32_t)(s0 + n*8 + lr)*144 + (ks*16 + lc*2)*2;
                uint32_t kbh[2], kbl[2];
                kbh[0] = *(const uint32_t*)(sma + AKH + off);
                kbh[1] = *(const uint32_t*)(sma + AKH + off + 16);
                kbl[0] = *(const uint32_t*)(sma + AKL + off);
                kbl[1] = *(const uint32_t*)(sma + AKL + off + 16);
                #pragma unroll
                for (int mt = 0; mt < 2; mt++) {
                    mma_bf16(S[mt][n], ah[mt], kbh);
                    mma_bf16(S[mt][n], ah[mt], kbl);
                    mma_bf16(S[mt][n], al[mt], kbh);
                }
            }
        }

        const bool diag = (c == w/2);
        #pragma unroll
        for (int mt = 0; mt < 2; mt++) {
            int trow = t0 + mt*16 + lr;
            #pragma unroll
            for (int n = 0; n < 8; n++) {
                int scol = s0 + n*8 + lc*2;
                S[mt][n][0] *= 0.125f; S[mt][n][1] *= 0.125f;
                S[mt][n][2] *= 0.125f; S[mt][n][3] *= 0.125f;
                if (diag) {
                    if (scol     > trow)     S[mt][n][0] = -1e30f;
                    if (scol + 1 > trow)     S[mt][n][1] = -1e30f;
                    if (scol     > trow + 8) S[mt][n][2] = -1e30f;
                    if (scol + 1 > trow + 8) S[mt][n][3] = -1e30f;
                }
            }
        }

        #pragma unroll
        for (int mt = 0; mt < 2; mt++) {
            #pragma unroll
            for (int rg = 0; rg < 2; rg++) {
                float cm = -1e30f;
                #pragma unroll
                for (int n = 0; n < 8; n++) {
                    cm = fmaxf(cm, S[mt][n][rg*2]);
                    cm = fmaxf(cm, S[mt][n][rg*2+1]);
                }
                cm = fmaxf(cm, __shfl_xor_sync(0xffffffffu, cm, 1));
                cm = fmaxf(cm, __shfl_xor_sync(0xffffffffu, cm, 2));
                float mold = mrow[mt][rg];
                float mn = fmaxf(mold, cm);
                float alpha = __expf(mold - mn);
                mrow[mt][rg] = mn;
                float ls = 0.f;
                #pragma unroll
                for (int n = 0; n < 8; n++) {
                    float p0 = __expf(S[mt][n][rg*2]   - mn);
                    float p1 = __expf(S[mt][n][rg*2+1] - mn);
                    S[mt][n][rg*2] = p0; S[mt][n][rg*2+1] = p1;
                    ls += p0 + p1;
                }
                lrow[mt][rg] = lrow[mt][rg]*alpha + ls;
                #pragma unroll
                for (int j = 0; j < 8; j++) {
                    O[mt][j][rg*2]   *= alpha;
                    O[mt][j][rg*2+1] *= alpha;
                }
            }
        }

        #pragma unroll
        for (int ks2 = 0; ks2 < 4; ks2++) {
            uint32_t ph[2][4], pl[2][4];
            #pragma unroll
            for (int mt = 0; mt < 2; mt++) {
                split2(S[mt][2*ks2][0],   S[mt][2*ks2][1],   ph[mt][0], pl[mt][0]);
                split2(S[mt][2*ks2][2],   S[mt][2*ks2][3],   ph[mt][1], pl[mt][1]);
                split2(S[mt][2*ks2+1][0], S[mt][2*ks2+1][1], ph[mt][2], pl[mt][2]);
                split2(S[mt][2*ks2+1][2], S[mt][2*ks2+1][3], ph[mt][3], pl[mt][3]);
            }
            #pragma unroll
            for (int j = 0; j < 8; j++) {
                uint32_t off = (uint32_t)(j*8 + lr)*528 + (s0 + ks2*16 + lc*2)*2;
                uint32_t vbh[2], vbl[2];
                vbh[0] = *(const uint32_t*)(sma + AVH + off);
                vbh[1] = *(const uint32_t*)(sma + AVH + off + 16);
                vbl[0] = *(const uint32_t*)(sma + AVL + off);
                vbl[1] = *(const uint32_t*)(sma + AVL + off + 16);
                #pragma unroll
                for (int mt = 0; mt < 2; mt++) {
                    mma_bf16(O[mt][j], ph[mt], vbh);
                    mma_bf16(O[mt][j], ph[mt], vbl);
                    mma_bf16(O[mt][j], pl[mt], vbh);
                }
            }
        }
    }

    float linv[2][2];
    #pragma unroll
    for (int mt = 0; mt < 2; mt++)
        #pragma unroll
        for (int rg = 0; rg < 2; rg++) {
            float lf = lrow[mt][rg];
            lf += __shfl_xor_sync(0xffffffffu, lf, 1);
            lf += __shfl_xor_sync(0xffffffffu, lf, 2);
            linv[mt][rg] = 1.f / lf;
        }
    const int b = bh / HH, h = bh % HH;
    #pragma unroll
    for (int mt = 0; mt < 2; mt++) {
        int r0 = t0 + mt*16 + lr;
        #pragma unroll
        for (int j = 0; j < 8; j++) {
            int d = j*8 + lc*2;
            uint32_t hi, lo;
            size_t o0 = ((size_t)(b*TT + r0))*CC + h*DD + d;
            split2(O[mt][j][0]*linv[mt][0], O[mt][j][1]*linv[mt][0], hi, lo);
            *(uint32_t*)(g_Athi + o0) = hi;  *(uint32_t*)(g_Atlo + o0) = lo;
            size_t o1 = ((size_t)(b*TT + r0 + 8))*CC + h*DD + d;
            split2(O[mt][j][2]*linv[mt][1], O[mt][j][3]*linv[mt][1], hi, lo);
            *(uint32_t*)(g_Athi + o1) = hi;  *(uint32_t*)(g_Atlo + o1) = lo;
        }
    }
}

// ---------------------------------------------------------------------------
extern "C" void kernel_launch(void* const* d_in, const int* in_sizes, int n_in,
                              void* d_out, int out_size) {
    const float* x  = (const float*)d_in[0];
    const float* Wq = (const float*)d_in[1];
    const float* Wk = (const float*)d_in[2];
    const float* Wv = (const float*)d_in[3];
    const float* Wp = (const float*)d_in[4];
    const float* bp = (const float*)d_in[5];
    float* out = (float*)d_out;

    split_x<<<(BT*CC/8 + 255)/256, 256>>>(x);
    pack_wt_kernel<<<(NQKV*CC + 255)/256, 256>>>(Wq, Wk, Wv);
    split_wp<<<(CC*CC/8 + 255)/256, 256>>>(Wp);

    const int gsmem = 2 * 4 * TILE_B;  // 81920
    cudaFuncSetAttribute(gemm_tc<0>, cudaFuncAttributeMaxDynamicSharedMemorySize, gsmem);
    cudaFuncSetAttribute(gemm_tc<1>, cudaFuncAttributeMaxDynamicSharedMemorySize, gsmem);

    gemm_tc<0><<<dim3(NQKV/128, BT/128), 256, gsmem>>>(nullptr, nullptr);

    cudaFuncSetAttribute(attn_flash, cudaFuncAttributeMaxDynamicSharedMemorySize, ASZ);
    attn_flash<<<BB*HH, 256, ASZ>>>();

    gemm_tc<1><<<dim3(CC/128, BT/128), 256, gsmem>>>(bp, out);
}

// round 9
// speedup vs baseline: 3.3106x; 1.1307x over previous
#include <cuda_runtime.h>
#include <cuda_bf16.h>
#include <cstdint>

#define BB 64
#define TT 256
#define CC 384
#define HH 6
#define DD 64
#define BT (BB*TT)         // 16384
#define NQKV (3*HH*DD)     // 1152
#define PITCH 40           // bf16 elems per smem/gmem tile row
#define TILE_E 5120        // elems per 128x32 tile (with pitch 40)
#define TILE_B 10240       // bytes per tile
#define NCH 12             // K chunks (384/32)

// attention smem layout (bytes). Q/K pitch 72 bf16 (144B), Vt pitch 264 bf16 (528B)
#define AQH 0
#define AQL 36864
#define AKH 73728
#define AKL 110592
#define AVH 147456
#define AVL 181248
#define ASZ 215040

// ---------------- static scratch (tiled/pitched layouts) ----------------
__device__ __align__(128) __nv_bfloat16 g_Xhi[(size_t)128*NCH*TILE_E], g_Xlo[(size_t)128*NCH*TILE_E];
__device__ __align__(128) __nv_bfloat16 g_Wthi[(size_t)9*NCH*TILE_E],  g_Wtlo[(size_t)9*NCH*TILE_E];
__device__ __align__(128) __nv_bfloat16 g_Athi[(size_t)128*NCH*TILE_E],g_Atlo[(size_t)128*NCH*TILE_E];
__device__ __align__(128) __nv_bfloat16 g_Wphi[(size_t)3*NCH*TILE_E],  g_Wplo[(size_t)3*NCH*TILE_E];
__device__ __align__(128) __nv_bfloat16 g_Qh[(size_t)BB*HH*TT*72], g_Ql[(size_t)BB*HH*TT*72];
__device__ __align__(128) __nv_bfloat16 g_Kh[(size_t)BB*HH*TT*72], g_Kl[(size_t)BB*HH*TT*72];
__device__ __align__(128) __nv_bfloat16 g_Vth[(size_t)BB*HH*DD*264], g_Vtl[(size_t)BB*HH*DD*264];

// ---------------- helpers ----------------
__device__ __forceinline__ void bulk_g2s(uint32_t dst, const void* src, uint32_t bytes,
                                         uint32_t mbar) {
    asm volatile("cp.async.bulk.shared::cluster.global.mbarrier::complete_tx::bytes "
                 "[%0], [%1], %2, [%3];"
                 :: "r"(dst), "l"(src), "r"(bytes), "r"(mbar) : "memory");
}
__device__ __forceinline__ void mbar_init(uint32_t mbar, uint32_t cnt) {
    asm volatile("mbarrier.init.shared.b64 [%0], %1;" :: "r"(mbar), "r"(cnt) : "memory");
}
__device__ __forceinline__ void mbar_expect(uint32_t mbar, uint32_t bytes) {
    asm volatile("mbarrier.arrive.expect_tx.shared.b64 _, [%0], %1;"
                 :: "r"(mbar), "r"(bytes) : "memory");
}
__device__ __forceinline__ void mbar_wait(uint32_t mbar, uint32_t parity) {
    asm volatile("{\n\t.reg .pred P;\n\t"
                 "WL_%=:\n\t"
                 "mbarrier.try_wait.parity.acquire.cta.shared::cta.b64 P, [%0], %1, 0x989680;\n\t"
                 "@P bra WD_%=;\n\t"
                 "bra WL_%=;\n\t"
                 "WD_%=:\n\t}"
                 :: "r"(mbar), "r"(parity) : "memory");
}
__device__ __forceinline__ void fence_async() {
    asm volatile("fence.proxy.async.shared::cta;" ::: "memory");
}
__device__ __forceinline__ void mma_bf16(float* c, const uint32_t* a, const uint32_t* b) {
    asm volatile("mma.sync.aligned.m16n8k16.row.col.f32.bf16.bf16.f32 "
                 "{%0,%1,%2,%3}, {%4,%5,%6,%7}, {%8,%9}, {%0,%1,%2,%3};"
                 : "+f"(c[0]), "+f"(c[1]), "+f"(c[2]), "+f"(c[3])
                 : "r"(a[0]), "r"(a[1]), "r"(a[2]), "r"(a[3]),
                   "r"(b[0]), "r"(b[1]));
}
__device__ __forceinline__ void ldm_x4(uint32_t* r, uint32_t addr) {
    asm volatile("ldmatrix.sync.aligned.m8n8.x4.shared.b16 {%0,%1,%2,%3}, [%4];"
                 : "=r"(r[0]), "=r"(r[1]), "=r"(r[2]), "=r"(r[3]) : "r"(addr));
}
__device__ __forceinline__ void split2(float x, float y, uint32_t& hi, uint32_t& lo) {
    __nv_bfloat16 hx = __float2bfloat16(x), hy = __float2bfloat16(y);
    __nv_bfloat16 lx = __float2bfloat16(x - __bfloat162float(hx));
    __nv_bfloat16 ly = __float2bfloat16(y - __bfloat162float(hy));
    uint16_t uhx = *(uint16_t*)&hx, uhy = *(uint16_t*)&hy;
    uint16_t ulx = *(uint16_t*)&lx, uly = *(uint16_t*)&ly;
    hi = (uint32_t)uhx | ((uint32_t)uhy << 16);
    lo = (uint32_t)ulx | ((uint32_t)uly << 16);
}
__device__ __forceinline__ size_t tiled_idx(int m, int k) {   // 128-row blocks, 32-col chunks
    return ((size_t)(m >> 7) * NCH + (k >> 5)) * TILE_E + (m & 127) * PITCH + (k & 31);
}

// ---------------- split / pack kernels (write tiled layouts) ----------------
__global__ void split_x(const float* __restrict__ src) {
    int i = (blockIdx.x * blockDim.x + threadIdx.x) * 8;
    if (i >= BT*CC) return;
    int m = i / CC, k = i % CC;
    float4 v0 = *(const float4*)(src + i);
    float4 v1 = *(const float4*)(src + i + 4);
    __nv_bfloat16 h[8], l[8];
    float vv[8] = {v0.x,v0.y,v0.z,v0.w,v1.x,v1.y,v1.z,v1.w};
    #pragma unroll
    for (int j = 0; j < 8; j++) {
        h[j] = __float2bfloat16(vv[j]);
        l[j] = __float2bfloat16(vv[j] - __bfloat162float(h[j]));
    }
    size_t d = tiled_idx(m, k);
    *(uint4*)(g_Xhi + d) = *(uint4*)h;
    *(uint4*)(g_Xlo + d) = *(uint4*)l;
}
__global__ void split_wp(const float* __restrict__ Wp) {
    int i = (blockIdx.x * blockDim.x + threadIdx.x) * 8;
    if (i >= CC*CC) return;
    int n = i / CC, k = i % CC;
    float4 v0 = *(const float4*)(Wp + i);
    float4 v1 = *(const float4*)(Wp + i + 4);
    __nv_bfloat16 h[8], l[8];
    float vv[8] = {v0.x,v0.y,v0.z,v0.w,v1.x,v1.y,v1.z,v1.w};
    #pragma unroll
    for (int j = 0; j < 8; j++) {
        h[j] = __float2bfloat16(vv[j]);
        l[j] = __float2bfloat16(vv[j] - __bfloat162float(h[j]));
    }
    size_t d = tiled_idx(n, k);
    *(uint4*)(g_Wphi + d) = *(uint4*)h;
    *(uint4*)(g_Wplo + d) = *(uint4*)l;
}
__global__ void pack_wt_kernel(const float* __restrict__ Wq,
                               const float* __restrict__ Wk,
                               const float* __restrict__ Wv) {
    int idx = blockIdx.x * blockDim.x + threadIdx.x;
    if (idx >= NQKV * CC) return;
    int n = idx / CC, c = idx % CC;
    int proj = n / (HH * DD), r = n % (HH * DD);
    int h = r / DD, d = r % DD;
    const float* W = (proj == 0) ? Wq : (proj == 1) ? Wk : Wv;
    float v = W[((size_t)h * CC + c) * DD + d];
    __nv_bfloat16 hi = __float2bfloat16(v);
    size_t di = tiled_idx(n, c);
    g_Wthi[di] = hi;
    g_Wtlo[di] = __float2bfloat16(v - __bfloat162float(hi));
}

// ---------------------------------------------------------------------------
// HMMA GEMM, cp.async.bulk staging (4 bulk ops/stage), ldmatrix fragments.
// MODE 0: A=Xtiled, B=Wttiled, emit Q,K (pitch 72) + Vt (pitch 264) hi/lo.
// MODE 1: A=Att tiled, B=Wp tiled, +bias -> fp32 out.
// ---------------------------------------------------------------------------
template<int MODE>
__global__ __launch_bounds__(256, 2) void gemm_tc(const float* __restrict__ bp,
                                                  float* __restrict__ outp) {
    extern __shared__ __align__(128) char sm[];
    const __nv_bfloat16* Ahi = (MODE == 0) ? g_Xhi  : g_Athi;
    const __nv_bfloat16* Alo = (MODE == 0) ? g_Xlo  : g_Atlo;
    const __nv_bfloat16* Bhi = (MODE == 0) ? g_Wthi : g_Wphi;
    const __nv_bfloat16* Blo = (MODE == 0) ? g_Wtlo : g_Wplo;

    const int tid = threadIdx.x, lane = tid & 31, wid = tid >> 5;
    const int wm = wid & 3, wn = wid >> 2;
    const int lr = lane >> 2, lc = lane & 3;
    const int rb = blockIdx.y, cb = blockIdx.x;
    const int row0 = rb * 128, col0 = cb * 128;
    const uint32_t sbase = (uint32_t)__cvta_generic_to_shared(sm);
    const uint32_t mb0 = sbase + 8*TILE_B, mb1 = mb0 + 8;

    uint32_t aoff[2];
    #pragma unroll
    for (int mt = 0; mt < 2; mt++)
        aoff[mt] = (uint32_t)(wm*32 + mt*16 + (lane & 15)) * PITCH + ((lane >> 4) & 1) * 8;
    uint32_t boff[4];
    #pragma unroll
    for (int jj = 0; jj < 4; jj++)
        boff[jj] = (uint32_t)(wn*64 + jj*16 + ((lane >> 4) & 1)*8 + (lane & 7)) * PITCH
                   + ((lane >> 3) & 1) * 8;

    if (tid == 0) { mbar_init(mb0, 1); mbar_init(mb1, 1); }
    __syncthreads();

    auto issue = [&](int buf, int c) {
        uint32_t st = sbase + buf * 4 * TILE_B;
        uint32_t mb = buf ? mb1 : mb0;
        fence_async();
        mbar_expect(mb, 4 * TILE_B);
        bulk_g2s(st + 0*TILE_B, Ahi + ((size_t)rb*NCH + c)*TILE_E, TILE_B, mb);
        bulk_g2s(st + 1*TILE_B, Alo + ((size_t)rb*NCH + c)*TILE_E, TILE_B, mb);
        bulk_g2s(st + 2*TILE_B, Bhi + ((size_t)cb*NCH + c)*TILE_E, TILE_B, mb);
        bulk_g2s(st + 3*TILE_B, Blo + ((size_t)cb*NCH + c)*TILE_E, TILE_B, mb);
    };

    float acc[2][8][4];
    #pragma unroll
    for (int i = 0; i < 2; i++)
        #pragma unroll
        for (int j = 0; j < 8; j++)
            #pragma unroll
            for (int r = 0; r < 4; r++) acc[i][j][r] = 0.f;

    if (tid == 0) { issue(0, 0); issue(1, 1); }

    for (int kc = 0; kc < NCH; kc++) {
        int buf = kc & 1;
        mbar_wait(buf ? mb1 : mb0, (kc >> 1) & 1);

        const uint32_t sbuf = sbase + buf * 4 * TILE_B;
        #pragma unroll
        for (int ks = 0; ks < 2; ks++) {
            const uint32_t kb = ks * 16;
            uint32_t ah[2][4], al[2][4];
            #pragma unroll
            for (int mt = 0; mt < 2; mt++) {
                uint32_t ad = sbuf + (aoff[mt] + kb) * 2;
                ldm_x4(ah[mt], ad);
                ldm_x4(al[mt], ad + TILE_B);
            }
            #pragma unroll
            for (int jj = 0; jj < 4; jj++) {
                uint32_t bd = sbuf + 2*TILE_B + (boff[jj] + kb) * 2;
                uint32_t bh4[4], bl4[4];
                ldm_x4(bh4, bd);
                ldm_x4(bl4, bd + TILE_B);
                #pragma unroll
                for (int mt = 0; mt < 2; mt++) {
                    mma_bf16(acc[mt][2*jj],   ah[mt], bh4);
                    mma_bf16(acc[mt][2*jj],   ah[mt], bl4);
                    mma_bf16(acc[mt][2*jj],   al[mt], bh4);
                    mma_bf16(acc[mt][2*jj+1], ah[mt], bh4 + 2);
                    mma_bf16(acc[mt][2*jj+1], ah[mt], bl4 + 2);
                    mma_bf16(acc[mt][2*jj+1], al[mt], bh4 + 2);
                }
            }
        }
        __syncthreads();
        if (tid == 0 && kc + 2 < NCH) issue(buf, kc + 2);
    }

    // epilogue
    #pragma unroll
    for (int i = 0; i < 2; i++) {
        int m0 = row0 + wm*32 + i*16 + lr;
        #pragma unroll
        for (int j = 0; j < 8; j++) {
            int nn = col0 + wn*64 + j*8 + lc*2;
            if (MODE == 0) {
                int proj = nn / (HH*DD);
                int rem  = nn % (HH*DD);
                int h = rem / DD, d = rem % DD;
                int b = m0 / TT, t = m0 % TT;
                int bh = b*HH + h;
                if (proj < 2) {
                    __nv_bfloat16* dh = (proj == 0) ? g_Qh : g_Kh;
                    __nv_bfloat16* dl = (proj == 0) ? g_Ql : g_Kl;
                    uint32_t h01, l01, h23, l23;
                    split2(acc[i][j][0], acc[i][j][1], h01, l01);
                    split2(acc[i][j][2], acc[i][j][3], h23, l23);
                    size_t o = ((size_t)bh*TT + t)*72 + d;
                    *(uint32_t*)(dh + o) = h01;          *(uint32_t*)(dl + o) = l01;
                    *(uint32_t*)(dh + o + 8*72) = h23;   *(uint32_t*)(dl + o + 8*72) = l23;
                } else {
                    size_t o = ((size_t)bh*DD + d)*264 + t;
                    float v00 = acc[i][j][0], v01 = acc[i][j][1];
                    float v10 = acc[i][j][2], v11 = acc[i][j][3];
                    __nv_bfloat16 hv, lv;
                    hv = __float2bfloat16(v00); lv = __float2bfloat16(v00 - __bfloat162float(hv));
                    g_Vth[o] = hv;               g_Vtl[o] = lv;
                    hv = __float2bfloat16(v01); lv = __float2bfloat16(v01 - __bfloat162float(hv));
                    g_Vth[o + 264] = hv;         g_Vtl[o + 264] = lv;
                    hv = __float2bfloat16(v10); lv = __float2bfloat16(v10 - __bfloat162float(hv));
                    g_Vth[o + 8] = hv;           g_Vtl[o + 8] = lv;
                    hv = __float2bfloat16(v11); lv = __float2bfloat16(v11 - __bfloat162float(hv));
                    g_Vth[o + 264 + 8] = hv;     g_Vtl[o + 264 + 8] = lv;
                }
            } else {
                float2 bb = *(const float2*)(bp + nn);
                *(float2*)(outp + (size_t)m0 * CC + nn) =
                    make_float2(acc[i][j][0] + bb.x, acc[i][j][1] + bb.y);
                *(float2*)(outp + (size_t)(m0 + 8) * CC + nn) =
                    make_float2(acc[i][j][2] + bb.x, acc[i][j][3] + bb.y);
            }
        }
    }
}

// ---------------------------------------------------------------------------
// HMMA flash attention: 1 CTA per (b,h); staging = 6 cp.async.bulk.
// Epilogue writes bf16 hi/lo att in TILED layout (feeds gemm<1> bulk loads).
// ---------------------------------------------------------------------------
__global__ __launch_bounds__(256, 1) void attn_flash() {
    extern __shared__ __align__(128) char sma[];
    const int bh = blockIdx.x;
    const int tid = threadIdx.x, lane = tid & 31, w = tid >> 5;
    const int lr = lane >> 2, lc = lane & 3;
    const uint32_t sb = (uint32_t)__cvta_generic_to_shared(sma);
    const uint32_t mb = sb + ASZ;

    if (tid == 0) {
        mbar_init(mb, 1);
        fence_async();
        mbar_expect(mb, ASZ);
        bulk_g2s(sb + AQH, g_Qh  + (size_t)bh*TT*72,  36864, mb);
        bulk_g2s(sb + AQL, g_Ql  + (size_t)bh*TT*72,  36864, mb);
        bulk_g2s(sb + AKH, g_Kh  + (size_t)bh*TT*72,  36864, mb);
        bulk_g2s(sb + AKL, g_Kl  + (size_t)bh*TT*72,  36864, mb);
        bulk_g2s(sb + AVH, g_Vth + (size_t)bh*DD*264, 33792, mb);
        bulk_g2s(sb + AVL, g_Vtl + (size_t)bh*DD*264, 33792, mb);
    }
    __syncthreads();
    mbar_wait(mb, 0);

    const int t0 = w * 32;
    float O[2][8][4];
    #pragma unroll
    for (int mt = 0; mt < 2; mt++)
        #pragma unroll
        for (int j = 0; j < 8; j++)
            #pragma unroll
            for (int r = 0; r < 4; r++) O[mt][j][r] = 0.f;
    float mrow[2][2] = {{-1e30f,-1e30f},{-1e30f,-1e30f}};
    float lrow[2][2] = {{0.f,0.f},{0.f,0.f}};

    const int nch = w/2 + 1;
    for (int c = 0; c < nch; c++) {
        const int s0 = c * 64;
        float S[2][8][4];
        #pragma unroll
        for (int mt = 0; mt < 2; mt++)
            #pragma unroll
            for (int n = 0; n < 8; n++)
                #pragma unroll
                for (int r = 0; r < 4; r++) S[mt][n][r] = 0.f;

        #pragma unroll
        for (int ks = 0; ks < 4; ks++) {
            uint32_t ah[2][4], al[2][4];
            #pragma unroll
            for (int mt = 0; mt < 2; mt++) {
                uint32_t off = (uint32_t)(t0 + mt*16 + lr)*144 + (ks*16 + lc*2)*2;
                ah[mt][0] = *(const uint32_t*)(sma + AQH + off);
                ah[mt][1] = *(const uint32_t*)(sma + AQH + off + 8*144);
                ah[mt][2] = *(const uint32_t*)(sma + AQH + off + 16);
                ah[mt][3] = *(const uint32_t*)(sma + AQH + off + 8*144 + 16);
                al[mt][0] = *(const uint32_t*)(sma + AQL + off);
                al[mt][1] = *(const uint32_t*)(sma + AQL + off + 8*144);
                al[mt][2] = *(const uint32_t*)(sma + AQL + off + 16);
                al[mt][3] = *(const uint32_t*)(sma + AQL + off + 8*144 + 16);
            }
            #pragma unroll
            for (int n = 0; n < 8; n++) {
                uint32_t off = (uint32_t)(s0 + n*8 + lr)*144 + (ks*16 + lc*2)*2;
                uint32_t kbh[2], kbl[2];
                kbh[0] = *(const uint32_t*)(sma + AKH + off);
                kbh[1] = *(const uint32_t*)(sma + AKH + off + 16);
                kbl[0] = *(const uint32_t*)(sma + AKL + off);
                kbl[1] = *(const uint32_t*)(sma + AKL + off + 16);
                #pragma unroll
                for (int mt = 0; mt < 2; mt++) {
                    mma_bf16(S[mt][n], ah[mt], kbh);
                    mma_bf16(S[mt][n], ah[mt], kbl);
                    mma_bf16(S[mt][n], al[mt], kbh);
                }
            }
        }

        const bool diag = (c == w/2);
        #pragma unroll
        for (int mt = 0; mt < 2; mt++) {
            int trow = t0 + mt*16 + lr;
            #pragma unroll
            for (int n = 0; n < 8; n++) {
                int scol = s0 + n*8 + lc*2;
                S[mt][n][0] *= 0.125f; S[mt][n][1] *= 0.125f;
                S[mt][n][2] *= 0.125f; S[mt][n][3] *= 0.125f;
                if (diag) {
                    if (scol     > trow)     S[mt][n][0] = -1e30f;
                    if (scol + 1 > trow)     S[mt][n][1] = -1e30f;
                    if (scol     > trow + 8) S[mt][n][2] = -1e30f;
                    if (scol + 1 > trow + 8) S[mt][n][3] = -1e30f;
                }
            }
        }

        #pragma unroll
        for (int mt = 0; mt < 2; mt++) {
            #pragma unroll
            for (int rg = 0; rg < 2; rg++) {
                float cm = -1e30f;
                #pragma unroll
                for (int n = 0; n < 8; n++) {
                    cm = fmaxf(cm, S[mt][n][rg*2]);
                    cm = fmaxf(cm, S[mt][n][rg*2+1]);
                }
                cm = fmaxf(cm, __shfl_xor_sync(0xffffffffu, cm, 1));
                cm = fmaxf(cm, __shfl_xor_sync(0xffffffffu, cm, 2));
                float mold = mrow[mt][rg];
                float mn = fmaxf(mold, cm);
                float alpha = __expf(mold - mn);
                mrow[mt][rg] = mn;
                float ls = 0.f;
                #pragma unroll
                for (int n = 0; n < 8; n++) {
                    float p0 = __expf(S[mt][n][rg*2]   - mn);
                    float p1 = __expf(S[mt][n][rg*2+1] - mn);
                    S[mt][n][rg*2] = p0; S[mt][n][rg*2+1] = p1;
                    ls += p0 + p1;
                }
                lrow[mt][rg] = lrow[mt][rg]*alpha + ls;
                #pragma unroll
                for (int j = 0; j < 8; j++) {
                    O[mt][j][rg*2]   *= alpha;
                    O[mt][j][rg*2+1] *= alpha;
                }
            }
        }

        #pragma unroll
        for (int ks2 = 0; ks2 < 4; ks2++) {
            uint32_t ph[2][4], pl[2][4];
            #pragma unroll
            for (int mt = 0; mt < 2; mt++) {
                split2(S[mt][2*ks2][0],   S[mt][2*ks2][1],   ph[mt][0], pl[mt][0]);
                split2(S[mt][2*ks2][2],   S[mt][2*ks2][3],   ph[mt][1], pl[mt][1]);
                split2(S[mt][2*ks2+1][0], S[mt][2*ks2+1][1], ph[mt][2], pl[mt][2]);
                split2(S[mt][2*ks2+1][2], S[mt][2*ks2+1][3], ph[mt][3], pl[mt][3]);
            }
            #pragma unroll
            for (int j = 0; j < 8; j++) {
                uint32_t off = (uint32_t)(j*8 + lr)*528 + (s0 + ks2*16 + lc*2)*2;
                uint32_t vbh[2], vbl[2];
                vbh[0] = *(const uint32_t*)(sma + AVH + off);
                vbh[1] = *(const uint32_t*)(sma + AVH + off + 16);
                vbl[0] = *(const uint32_t*)(sma + AVL + off);
                vbl[1] = *(const uint32_t*)(sma + AVL + off + 16);
                #pragma unroll
                for (int mt = 0; mt < 2; mt++) {
                    mma_bf16(O[mt][j], ph[mt], vbh);
                    mma_bf16(O[mt][j], ph[mt], vbl);
                    mma_bf16(O[mt][j], pl[mt], vbh);
                }
            }
        }
    }

    float linv[2][2];
    #pragma unroll
    for (int mt = 0; mt < 2; mt++)
        #pragma unroll
        for (int rg = 0; rg < 2; rg++) {
            float lf = lrow[mt][rg];
            lf += __shfl_xor_sync(0xffffffffu, lf, 1);
            lf += __shfl_xor_sync(0xffffffffu, lf, 2);
            linv[mt][rg] = 1.f / lf;
        }
    const int b = bh / HH, h = bh % HH;
    #pragma unroll
    for (int mt = 0; mt < 2; mt++) {
        int r0 = t0 + mt*16 + lr;
        #pragma unroll
        for (int j = 0; j < 8; j++) {
            int d = j*8 + lc*2;
            int n = h*DD + d;
            int gm0 = b*TT + r0;
            uint32_t hi, lo;
            size_t o0 = tiled_idx(gm0, n);
            split2(O[mt][j][0]*linv[mt][0], O[mt][j][1]*linv[mt][0], hi, lo);
            *(uint32_t*)(g_Athi + o0) = hi;  *(uint32_t*)(g_Atlo + o0) = lo;
            size_t o1 = tiled_idx(gm0 + 8, n);
            split2(O[mt][j][2]*linv[mt][1], O[mt][j][3]*linv[mt][1], hi, lo);
            *(uint32_t*)(g_Athi + o1) = hi;  *(uint32_t*)(g_Atlo + o1) = lo;
        }
    }
}

// ---------------------------------------------------------------------------
extern "C" void kernel_launch(void* const* d_in, const int* in_sizes, int n_in,
                              void* d_out, int out_size) {
    const float* x  = (const float*)d_in[0];
    const float* Wq = (const float*)d_in[1];
    const float* Wk = (const float*)d_in[2];
    const float* Wv = (const float*)d_in[3];
    const float* Wp = (const float*)d_in[4];
    const float* bp = (const float*)d_in[5];
    float* out = (float*)d_out;

    split_x<<<(BT*CC/8 + 255)/256, 256>>>(x);
    pack_wt_kernel<<<(NQKV*CC + 255)/256, 256>>>(Wq, Wk, Wv);
    split_wp<<<(CC*CC/8 + 255)/256, 256>>>(Wp);

    const int gsmem = 8 * TILE_B + 16;   // 2 buffers x 4 tiles + 2 mbarriers
    cudaFuncSetAttribute(gemm_tc<0>, cudaFuncAttributeMaxDynamicSharedMemorySize, gsmem);
    cudaFuncSetAttribute(gemm_tc<1>, cudaFuncAttributeMaxDynamicSharedMemorySize, gsmem);

    gemm_tc<0><<<dim3(NQKV/128, BT/128), 256, gsmem>>>(nullptr, nullptr);

    cudaFuncSetAttribute(attn_flash, cudaFuncAttributeMaxDynamicSharedMemorySize, ASZ + 16);
    attn_flash<<<BB*HH, 256, ASZ + 16>>>();

    gemm_tc<1><<<dim3(CC/128, BT/128), 256, gsmem>>>(bp, out);
}